// round 13
// baseline (speedup 1.0000x reference)
#include <cuda_runtime.h>
#include <cuda_fp16.h>
#include <math.h>
#include <stdint.h>

#define Hdim 128
#define Wdim 128
#define Cdim 128
#define NPIX (Hdim * Wdim)
#define HEADS 4
#define HD 32
#define KW 7
#define KK 49
#define RPBW 13
#define QSCALE 0.17677669529663689f

// ---------------- scratch ----------------
__device__ float  g_x2 [NPIX * Cdim];
__device__ __half g_qh [NPIX * Cdim];
__device__ __half g_vh [NPIX * Cdim];
__device__ __half g_kh [NPIX * Cdim];
__device__ __half s_xn [NPIX * Cdim];
__device__ __half s_yh [NPIX * Cdim];
__device__ __half s_att[NPIX * Cdim];
__device__ __half s_h  [NPIX * 512];
// weights fp16: qv@0 (32768), k@32768, proj@49152, fc1@65536, fc2@131072
__device__ __half s_w  [196608];

// ---------------- helpers ----------------
__device__ __forceinline__ uint32_t smem_u32(const void* p) {
    uint32_t a;
    asm("{ .reg .u64 t; cvta.to.shared.u64 t, %1; cvt.u32.u64 %0, t; }" : "=r"(a) : "l"(p));
    return a;
}
__device__ __forceinline__ void ldm_x4(uint32_t& r0, uint32_t& r1, uint32_t& r2, uint32_t& r3,
                                       uint32_t addr) {
    asm volatile("ldmatrix.sync.aligned.m8n8.x4.shared.b16 {%0,%1,%2,%3}, [%4];"
        : "=r"(r0), "=r"(r1), "=r"(r2), "=r"(r3) : "r"(addr));
}
__device__ __forceinline__ void mma_f16(float* d, const uint32_t* a, const uint32_t* b) {
    asm volatile("mma.sync.aligned.m16n8k16.row.col.f32.f16.f16.f32 "
        "{%0,%1,%2,%3}, {%4,%5,%6,%7}, {%8,%9}, {%0,%1,%2,%3};"
        : "+f"(d[0]), "+f"(d[1]), "+f"(d[2]), "+f"(d[3])
        : "r"(a[0]), "r"(a[1]), "r"(a[2]), "r"(a[3]), "r"(b[0]), "r"(b[1]));
}
__device__ __forceinline__ void cp16(uint32_t dst, const void* src) {
    asm volatile("cp.async.cg.shared.global [%0], [%1], 16;" :: "r"(dst), "l"(src));
}
#define CP_COMMIT() asm volatile("cp.async.commit_group;" ::: "memory")
#define CP_WAIT(n)  asm volatile("cp.async.wait_group %0;" :: "n"(n) : "memory")
__device__ __forceinline__ uint32_t pack_h2(float a, float b) {
    __half2 t = __floats2half2_rn(a, b);
    return *(uint32_t*)&t;
}

// ---------------- prep: LN1 + y->fp16 + w->fp16 ----------------
__global__ void prep_kernel(const float* __restrict__ x,
                            const float* __restrict__ n1w, const float* __restrict__ n1b,
                            const float* __restrict__ y,
                            const float* __restrict__ qvw, const float* __restrict__ kw,
                            const float* __restrict__ pw,  const float* __restrict__ f1,
                            const float* __restrict__ f2,
                            __half* __restrict__ xn, __half* __restrict__ yh,
                            __half* __restrict__ wdst)
{
    const int b = blockIdx.x, tid = threadIdx.x;
    if (b < 8192) {
        const int row = b * 2 + (tid >> 7);
        const int r = tid & 127;
        float v = x[row * Cdim + r];
        float s = v, s2 = v * v;
        #pragma unroll
        for (int o = 16; o; o >>= 1) {
            s  += __shfl_xor_sync(0xffffffffu, s,  o);
            s2 += __shfl_xor_sync(0xffffffffu, s2, o);
        }
        __shared__ float ss[8], ss2[8];
        const int wrp = tid >> 5;
        if ((tid & 31) == 0) { ss[wrp] = s; ss2[wrp] = s2; }
        __syncthreads();
        const int base = (tid >> 7) * 4;
        s  = ss[base]  + ss[base + 1]  + ss[base + 2]  + ss[base + 3];
        s2 = ss2[base] + ss2[base + 1] + ss2[base + 2] + ss2[base + 3];
        float mu  = s * (1.0f / Cdim);
        float var = s2 * (1.0f / Cdim) - mu * mu;
        float rr = (v - mu) * rsqrtf(var + 1e-5f) * n1w[r] + n1b[r];
        xn[row * Cdim + r] = __float2half(rr);
    } else if (b < 12288) {
        const int i = (b - 8192) * 512 + tid * 2;
        yh[i]     = __float2half(y[i]);
        yh[i + 1] = __float2half(y[i + 1]);
    } else {
        const int wi = (b - 12288) * 512 + tid * 2;
        #pragma unroll
        for (int e = 0; e < 2; e++) {
            int q = wi + e;
            if (q < 196608) {
                float v;
                if      (q < 32768)  v = qvw[q];
                else if (q < 49152)  v = kw [q - 32768];
                else if (q < 65536)  v = pw [q - 49152];
                else if (q < 131072) v = f1 [q - 65536];
                else                 v = f2 [q - 131072];
                wdst[q] = __float2half(v);
            }
        }
    }
}

// ---------------- GEMM core 64x64 (fc2) ----------
#define OFF_W  9216
#define STAGE  18432
#define GSMEM  (2 * STAGE)

template <int KTOT>
__device__ __forceinline__ void gemm_core(
    const __half* __restrict__ A, const __half* __restrict__ W,
    int bm, int bn, uint32_t sb, float acc[2][4][4])
{
    const int tid = threadIdx.x, lane = tid & 31, wid = tid >> 5;
    const int wm = wid & 1, wn = wid >> 1;
    const int nch = KTOT / 64;

    #pragma unroll
    for (int i = 0; i < 2; i++)
        #pragma unroll
        for (int j = 0; j < 4; j++)
            #pragma unroll
            for (int q = 0; q < 4; q++) acc[i][j][q] = 0.0f;

    const uint32_t aRow = wm * 32 + (lane & 15);
    const uint32_t aKof = ((lane >> 4) << 3);
    const uint32_t bRow = wn * 32 + ((lane >> 4) << 3) + (lane & 7);
    const uint32_t bKof = ((lane >> 3) & 1) << 3;

    #pragma unroll
    for (int t = tid; t < 1024; t += 128) {
        const int isW = t >> 9;
        const int u = t & 511, row = u >> 3, c8 = u & 7;
        const uint32_t dst = sb + isW * OFF_W + row * 144 + c8 * 16;
        const __half* src = (isW ? W : A) +
            (size_t)((isW ? bn : bm) * 64 + row) * KTOT + c8 * 8;
        cp16(dst, src);
    }
    CP_COMMIT();

    for (int ch = 0; ch < nch; ch++) {
        if (ch + 1 < nch) {
            const uint32_t st = sb + ((ch + 1) & 1) * STAGE;
            const int kb = (ch + 1) * 64;
            #pragma unroll
            for (int t = tid; t < 1024; t += 128) {
                const int isW = t >> 9;
                const int u = t & 511, row = u >> 3, c8 = u & 7;
                const uint32_t dst = st + isW * OFF_W + row * 144 + c8 * 16;
                const __half* src = (isW ? W : A) +
                    (size_t)((isW ? bn : bm) * 64 + row) * KTOT + kb + c8 * 8;
                cp16(dst, src);
            }
            CP_COMMIT();
            CP_WAIT(1);
        } else {
            CP_WAIT(0);
        }
        __syncthreads();

        const uint32_t st = sb + (ch & 1) * STAGE;
        #pragma unroll
        for (int ks = 0; ks < 4; ks++) {
            const uint32_t aoff = st + (aRow * 72 + ks * 16 + aKof) * 2;
            const uint32_t boff = st + OFF_W + (bRow * 72 + ks * 16 + bKof) * 2;
            uint32_t a0[4], a1[4], w0[4], w1[4];
            ldm_x4(a0[0], a0[1], a0[2], a0[3], aoff);
            ldm_x4(a1[0], a1[1], a1[2], a1[3], aoff + 16 * 144);
            ldm_x4(w0[0], w0[1], w0[2], w0[3], boff);
            ldm_x4(w1[0], w1[1], w1[2], w1[3], boff + 16 * 144);

            mma_f16(acc[0][0], a0, w0); mma_f16(acc[0][1], a0, w0 + 2);
            mma_f16(acc[0][2], a0, w1); mma_f16(acc[0][3], a0, w1 + 2);
            mma_f16(acc[1][0], a1, w0); mma_f16(acc[1][1], a1, w0 + 2);
            mma_f16(acc[1][2], a1, w1); mma_f16(acc[1][3], a1, w1 + 2);
        }
        __syncthreads();
    }
}

// ---------------- GEMM core 64x128 (qvk, fc1) ----------
#define OFF_W2 9216
#define STAGE2 27648
#define GSMEM2 (2 * STAGE2)

template <int KTOT>
__device__ __forceinline__ void gemm_core_n128(
    const __half* __restrict__ A, const __half* __restrict__ W,
    int bm, uint32_t sb, float acc[2][8][4])
{
    const int tid = threadIdx.x, lane = tid & 31, wid = tid >> 5;
    const int wm = wid & 1, wn = wid >> 1;
    const int nch = KTOT / 64;

    #pragma unroll
    for (int i = 0; i < 2; i++)
        #pragma unroll
        for (int j = 0; j < 8; j++)
            #pragma unroll
            for (int q = 0; q < 4; q++) acc[i][j][q] = 0.0f;

    const uint32_t aRow = wm * 32 + (lane & 15);
    const uint32_t aKof = ((lane >> 4) << 3);
    const uint32_t bRow = wn * 64 + ((lane >> 4) << 3) + (lane & 7);
    const uint32_t bKof = ((lane >> 3) & 1) << 3;

    #pragma unroll
    for (int t = tid; t < 1536; t += 128) {
        const int isW = t >= 512;
        const int u = isW ? (t - 512) : t;
        const int row = u >> 3, c8 = u & 7;
        const uint32_t dst = sb + (isW ? OFF_W2 : 0) + row * 144 + c8 * 16;
        const __half* src = isW ? (W + (size_t)row * KTOT + c8 * 8)
                                : (A + (size_t)(bm * 64 + row) * KTOT + c8 * 8);
        cp16(dst, src);
    }
    CP_COMMIT();

    for (int ch = 0; ch < nch; ch++) {
        if (ch + 1 < nch) {
            const uint32_t st = sb + ((ch + 1) & 1) * STAGE2;
            const int kb = (ch + 1) * 64;
            #pragma unroll
            for (int t = tid; t < 1536; t += 128) {
                const int isW = t >= 512;
                const int u = isW ? (t - 512) : t;
                const int row = u >> 3, c8 = u & 7;
                const uint32_t dst = st + (isW ? OFF_W2 : 0) + row * 144 + c8 * 16;
                const __half* src = isW ? (W + (size_t)row * KTOT + kb + c8 * 8)
                                        : (A + (size_t)(bm * 64 + row) * KTOT + kb + c8 * 8);
                cp16(dst, src);
            }
            CP_COMMIT();
            CP_WAIT(1);
        } else {
            CP_WAIT(0);
        }
        __syncthreads();

        const uint32_t st = sb + (ch & 1) * STAGE2;
        #pragma unroll
        for (int ks = 0; ks < 4; ks++) {
            const uint32_t aoff = st + (aRow * 72 + ks * 16 + aKof) * 2;
            uint32_t a0[4], a1[4];
            ldm_x4(a0[0], a0[1], a0[2], a0[3], aoff);
            ldm_x4(a1[0], a1[1], a1[2], a1[3], aoff + 16 * 144);
            uint32_t wf[4][4];
            #pragma unroll
            for (int nf4 = 0; nf4 < 4; nf4++) {
                const uint32_t boff = st + OFF_W2 +
                    ((bRow + nf4 * 16) * 72 + ks * 16 + bKof) * 2;
                ldm_x4(wf[nf4][0], wf[nf4][1], wf[nf4][2], wf[nf4][3], boff);
            }
            #pragma unroll
            for (int nf4 = 0; nf4 < 4; nf4++) {
                mma_f16(acc[0][nf4 * 2],     a0, wf[nf4]);
                mma_f16(acc[0][nf4 * 2 + 1], a0, wf[nf4] + 2);
            }
            #pragma unroll
            for (int nf4 = 0; nf4 < 4; nf4++) {
                mma_f16(acc[1][nf4 * 2],     a1, wf[nf4]);
                mma_f16(acc[1][nf4 * 2 + 1], a1, wf[nf4] + 2);
            }
        }
        __syncthreads();
    }
}

// ---------------- GEMM core 32x128 (proj_ln) ----------
// 4 warps, warp = 32 rows x 32 cols. A 32x64 chunk + W 128x64 chunk staged.
#define OFF_W3 4608                    // A buffer: 32*144
#define STAGE3 23040                   // + 128*144
#define GSMEM3 (2 * STAGE3)

template <int KTOT>
__device__ __forceinline__ void gemm_core_m32(
    const __half* __restrict__ A, const __half* __restrict__ W,
    int bm, uint32_t sb, float acc[2][4][4])
{
    const int tid = threadIdx.x, lane = tid & 31, wn = tid >> 5;
    const int nch = KTOT / 64;

    #pragma unroll
    for (int i = 0; i < 2; i++)
        #pragma unroll
        for (int j = 0; j < 4; j++)
            #pragma unroll
            for (int q = 0; q < 4; q++) acc[i][j][q] = 0.0f;

    const uint32_t aRow = (lane & 15);
    const uint32_t aKof = ((lane >> 4) << 3);
    const uint32_t bRow = wn * 32 + ((lane >> 4) << 3) + (lane & 7);
    const uint32_t bKof = ((lane >> 3) & 1) << 3;

    // stage 0: A 256 tasks + W 1024 tasks = 1280
    #pragma unroll
    for (int t = tid; t < 1280; t += 128) {
        const int isW = t >= 256;
        const int u = isW ? (t - 256) : t;
        const int row = u >> 3, c8 = u & 7;
        const uint32_t dst = sb + (isW ? OFF_W3 : 0) + row * 144 + c8 * 16;
        const __half* src = isW ? (W + (size_t)row * KTOT + c8 * 8)
                                : (A + (size_t)(bm * 32 + row) * KTOT + c8 * 8);
        cp16(dst, src);
    }
    CP_COMMIT();

    for (int ch = 0; ch < nch; ch++) {
        if (ch + 1 < nch) {
            const uint32_t st = sb + ((ch + 1) & 1) * STAGE3;
            const int kb = (ch + 1) * 64;
            #pragma unroll
            for (int t = tid; t < 1280; t += 128) {
                const int isW = t >= 256;
                const int u = isW ? (t - 256) : t;
                const int row = u >> 3, c8 = u & 7;
                const uint32_t dst = st + (isW ? OFF_W3 : 0) + row * 144 + c8 * 16;
                const __half* src = isW ? (W + (size_t)row * KTOT + kb + c8 * 8)
                                        : (A + (size_t)(bm * 32 + row) * KTOT + kb + c8 * 8);
                cp16(dst, src);
            }
            CP_COMMIT();
            CP_WAIT(1);
        } else {
            CP_WAIT(0);
        }
        __syncthreads();

        const uint32_t st = sb + (ch & 1) * STAGE3;
        #pragma unroll
        for (int ks = 0; ks < 4; ks++) {
            const uint32_t aoff = st + (aRow * 72 + ks * 16 + aKof) * 2;
            const uint32_t boff = st + OFF_W3 + (bRow * 72 + ks * 16 + bKof) * 2;
            uint32_t a0[4], a1[4], b0[4], b1[4];
            ldm_x4(a0[0], a0[1], a0[2], a0[3], aoff);
            ldm_x4(a1[0], a1[1], a1[2], a1[3], aoff + 16 * 144);
            ldm_x4(b0[0], b0[1], b0[2], b0[3], boff);
            ldm_x4(b1[0], b1[1], b1[2], b1[3], boff + 16 * 144);

            mma_f16(acc[0][0], a0, b0); mma_f16(acc[0][1], a0, b0 + 2);
            mma_f16(acc[0][2], a0, b1); mma_f16(acc[0][3], a0, b1 + 2);
            mma_f16(acc[1][0], a1, b0); mma_f16(acc[1][1], a1, b0 + 2);
            mma_f16(acc[1][2], a1, b1); mma_f16(acc[1][3], a1, b1 + 2);
        }
        __syncthreads();
    }
}

// ---------------- fused qv + k GEMM (n128 tiles) ---------------------------
__global__ __launch_bounds__(128, 4)
void gemm_qvk(const __half* __restrict__ xn, const __half* __restrict__ yh,
              const __half* __restrict__ wbuf,
              const float* __restrict__ qv_b, const float* __restrict__ k_b,
              __half* __restrict__ qout,
              __half* __restrict__ vout, __half* __restrict__ kout)
{
    extern __shared__ __align__(16) char dsm[];
    const uint32_t sb = smem_u32(dsm);
    const int bx = blockIdx.x, bm = blockIdx.y;
    float acc[2][8][4];
    const __half* A = (bx == 2) ? yh : xn;
    const __half* W = (bx == 0) ? wbuf : (bx == 1 ? wbuf + 16384 : wbuf + 32768);
    gemm_core_n128<128>(A, W, bm, sb, acc);

    const float* bias = (bx == 0) ? qv_b : (bx == 1 ? qv_b + 128 : k_b);
    __half* outp = (bx == 0) ? qout : (bx == 1 ? vout : kout);
    const float qs = (bx == 0) ? QSCALE : 1.0f;

    const int tid = threadIdx.x, lane = tid & 31, wid = tid >> 5;
    const int wm = wid & 1, wn = wid >> 1;
    #pragma unroll
    for (int mf = 0; mf < 2; mf++) {
        const int row0 = bm * 64 + wm * 32 + mf * 16 + (lane >> 2);
        #pragma unroll
        for (int nf = 0; nf < 8; nf++) {
            const int col = wn * 64 + nf * 8 + (lane & 3) * 2;
            float* a = acc[mf][nf];
            float2 bi = *(const float2*)&bias[col];
            *(uint32_t*)&outp[(size_t)row0 * 128 + col] =
                pack_h2((a[0] + bi.x) * qs, (a[1] + bi.y) * qs);
            *(uint32_t*)&outp[(size_t)(row0 + 8) * 128 + col] =
                pack_h2((a[2] + bi.x) * qs, (a[3] + bi.y) * qs);
        }
    }
}

// ---------------- proj GEMM (32x128) + residual + fused LN2 ----------------
__global__ __launch_bounds__(128, 4)
void gemm_proj_ln(const __half* __restrict__ A, const __half* __restrict__ W,
                  const float* __restrict__ bias, const float* __restrict__ res,
                  const float* __restrict__ n2w, const float* __restrict__ n2b,
                  float* __restrict__ x2out, __half* __restrict__ xnout)
{
    extern __shared__ __align__(16) char dsm[];
    const uint32_t sb = smem_u32(dsm);
    const int bm = blockIdx.x;
    float acc[2][4][4];
    gemm_core_m32<128>(A, W, bm, sb, acc);

    const int tid = threadIdx.x, lane = tid & 31, wn = tid >> 5;
    float* xs = (float*)dsm;    // 32 x 132 fp32 (16.9 KB, fits stage area)

    #pragma unroll
    for (int mf = 0; mf < 2; mf++) {
        const int lr = mf * 16 + (lane >> 2);
        const int grow = bm * 32 + lr;
        #pragma unroll
        for (int nf = 0; nf < 4; nf++) {
            const int col = wn * 32 + nf * 8 + (lane & 3) * 2;
            float* a = acc[mf][nf];
            float2 bi = *(const float2*)&bias[col];
            float2 r0 = *(const float2*)&res[(size_t)grow * 128 + col];
            float2 r1 = *(const float2*)&res[(size_t)(grow + 8) * 128 + col];
            float v0 = a[0] + bi.x + r0.x, v1 = a[1] + bi.y + r0.y;
            float v2 = a[2] + bi.x + r1.x, v3 = a[3] + bi.y + r1.y;
            *(float2*)&x2out[(size_t)grow * 128 + col]       = make_float2(v0, v1);
            *(float2*)&x2out[(size_t)(grow + 8) * 128 + col] = make_float2(v2, v3);
            xs[lr * 132 + col] = v0;       xs[lr * 132 + col + 1] = v1;
            xs[(lr + 8) * 132 + col] = v2; xs[(lr + 8) * 132 + col + 1] = v3;
        }
    }
    __syncthreads();

    // LN2: warp-per-row (8 rows per warp), conflict-free float4 lanes
    const float4 w4 = *(const float4*)&n2w[lane * 4];
    const float4 b4 = *(const float4*)&n2b[lane * 4];
    for (int i = 0; i < 8; i++) {
        const int row = wn * 8 + i;
        float4 v = *(const float4*)&xs[row * 132 + lane * 4];
        float s  = v.x + v.y + v.z + v.w;
        float s2 = v.x * v.x + v.y * v.y + v.z * v.z + v.w * v.w;
        #pragma unroll
        for (int o = 16; o; o >>= 1) {
            s  += __shfl_xor_sync(0xffffffffu, s,  o);
            s2 += __shfl_xor_sync(0xffffffffu, s2, o);
        }
        const float mu  = s * (1.0f / 128.0f);
        const float var = s2 * (1.0f / 128.0f) - mu * mu;
        const float rs  = rsqrtf(var + 1e-5f);
        const int grow = bm * 32 + row;
        uint2 o2;
        o2.x = pack_h2((v.x - mu) * rs * w4.x + b4.x, (v.y - mu) * rs * w4.y + b4.y);
        o2.y = pack_h2((v.z - mu) * rs * w4.z + b4.z, (v.w - mu) * rs * w4.w + b4.w);
        *(uint2*)&xnout[(size_t)grow * 128 + lane * 4] = o2;
    }
}

// ---------------- fc1 (n128 tiles): GEMM + GELU -> fp16 ----------------
__global__ __launch_bounds__(128, 4)
void gemm_gelu(const __half* __restrict__ A, const __half* __restrict__ wbuf,
               const float* __restrict__ bias,
               __half* __restrict__ o)
{
    extern __shared__ __align__(16) char dsm[];
    const uint32_t sb = smem_u32(dsm);
    const int bn = blockIdx.x, bm = blockIdx.y;
    float acc[2][8][4];
    gemm_core_n128<128>(A, wbuf + (size_t)bn * 128 * 128, bm, sb, acc);

    const int tid = threadIdx.x, lane = tid & 31, wid = tid >> 5;
    const int wm = wid & 1, wn = wid >> 1;
    #pragma unroll
    for (int mf = 0; mf < 2; mf++) {
        const int row0 = bm * 64 + wm * 32 + mf * 16 + (lane >> 2);
        #pragma unroll
        for (int nf = 0; nf < 8; nf++) {
            const int col = bn * 128 + wn * 64 + nf * 8 + (lane & 3) * 2;
            float* a = acc[mf][nf];
            float2 bi = *(const float2*)&bias[col];
            float v[4];
            v[0] = a[0] + bi.x; v[1] = a[1] + bi.y;
            v[2] = a[2] + bi.x; v[3] = a[3] + bi.y;
            #pragma unroll
            for (int e = 0; e < 4; e++)
                v[e] = 0.5f * v[e] * (1.0f + erff(v[e] * 0.70710678118654752f));
            *(uint32_t*)&o[(size_t)row0 * 512 + col]       = pack_h2(v[0], v[1]);
            *(uint32_t*)&o[(size_t)(row0 + 8) * 512 + col] = pack_h2(v[2], v[3]);
        }
    }
}

// ---------------- fc2 (64x64, K=512): GEMM + residual -> out ---------------
__global__ __launch_bounds__(128, 5)
void gemm_res2(const __half* __restrict__ A, const __half* __restrict__ W,
               const float* __restrict__ bias, const float* __restrict__ res,
               float* __restrict__ outf)
{
    extern __shared__ __align__(16) char dsm[];
    const uint32_t sb = smem_u32(dsm);
    const int bn = blockIdx.x, bm = blockIdx.y;
    float acc[2][4][4];
    gemm_core<512>(A, W, bm, bn, sb, acc);

    const int tid = threadIdx.x, lane = tid & 31, wid = tid >> 5;
    const int wm = wid & 1, wn = wid >> 1;
    #pragma unroll
    for (int mf = 0; mf < 2; mf++) {
        const int row0 = bm * 64 + wm * 32 + mf * 16 + (lane >> 2);
        #pragma unroll
        for (int nf = 0; nf < 4; nf++) {
            const int col = bn * 64 + wn * 32 + nf * 8 + (lane & 3) * 2;
            float* a = acc[mf][nf];
            float2 bi = *(const float2*)&bias[col];
            float2 r0 = *(const float2*)&res[(size_t)row0 * 128 + col];
            float2 r1 = *(const float2*)&res[(size_t)(row0 + 8) * 128 + col];
            *(float2*)&outf[(size_t)row0 * 128 + col] =
                make_float2(a[0] + bi.x + r0.x, a[1] + bi.y + r0.y);
            *(float2*)&outf[(size_t)(row0 + 8) * 128 + col] =
                make_float2(a[2] + bi.x + r1.x, a[3] + bi.y + r1.y);
        }
    }
}

// ------- neighborhood attention: full half2 arithmetic (proven) --------
#define NBW 22
#define NBH 14
#define NBR (NBW * NBH)
#define KVP 40

__global__ __launch_bounds__(128)
void attn_kernel(const __half* __restrict__ qbuf,
                 const __half* __restrict__ vbuf,
                 const __half* __restrict__ kbuf,
                 const float* __restrict__ rpb,
                 __half* __restrict__ obuf)
{
    __shared__ __align__(16) __half kv_s[NBR * KVP];
    __shared__ float rpb_s[RPBW * RPBW];

    const int hd = blockIdx.z;
    const int bw = blockIdx.x * 16, bh = blockIdx.y * 8;
    const int tid = threadIdx.x;
    const int px = tid & 15, py = tid >> 4;
    const int h = bh + py, w = bw + px;
    const int o_h = min(max(bh - 3, 0), Hdim - NBH);
    const int o_w = min(max(bw - 3, 0), Wdim - NBW);

    for (int i = tid; i < RPBW * RPBW; i += 128) rpb_s[i] = rpb[hd * RPBW * RPBW + i];

    for (int idx = tid; idx < NBR * 4; idx += 128) {
        const int rr = idx >> 2, j = idx & 3;
        const int gh = o_h + rr / NBW, gw = o_w + rr % NBW;
        *(uint4*)&kv_s[rr * KVP + j * 8] =
            *(const uint4*)&kbuf[(size_t)(gh * Wdim + gw) * Cdim + hd * HD + j * 8];
    }
    __syncthreads();

    uint32_t qw[16];
    {
        const uint4* qp = (const uint4*)&qbuf[(size_t)(h * Wdim + w) * Cdim + hd * HD];
        #pragma unroll
        for (int j = 0; j < 4; j++) {
            uint4 t = qp[j];
            qw[j * 4] = t.x; qw[j * 4 + 1] = t.y; qw[j * 4 + 2] = t.z; qw[j * 4 + 3] = t.w;
        }
    }

    const int sh = min(max(h - 3, 0), Hdim - KW);
    const int sw = min(max(w - 3, 0), Wdim - KW);
    const int lr0 = sh - o_h, lc0 = sw - o_w;
    const int rh0 = sh - h + 6, rw0 = sw - w + 6;

    float p[KK];
    #pragma unroll
    for (int a = 0; a < KW; a++) {
        #pragma unroll
        for (int c = 0; c < KW; c++) {
            const uint4* kp = (const uint4*)&kv_s[((lr0 + a) * NBW + lc0 + c) * KVP];
            __half2 d0 = __float2half2_rn(0.f), d1 = d0, d2 = d0, d3 = d0;
            #pragma unroll
            for (int j = 0; j < 4; j++) {
                uint4 t = kp[j];
                d0 = __hfma2(*(__half2*)&qw[j*4+0], *(__half2*)&t.x, d0);
                d1 = __hfma2(*(__half2*)&qw[j*4+1], *(__half2*)&t.y, d1);
                d2 = __hfma2(*(__half2*)&qw[j*4+2], *(__half2*)&t.z, d2);
                d3 = __hfma2(*(__half2*)&qw[j*4+3], *(__half2*)&t.w, d3);
            }
            __half2 ds = __hadd2(__hadd2(d0, d1), __hadd2(d2, d3));
            p[a * KW + c] = __low2float(ds) + __high2float(ds)
                          + rpb_s[(rh0 + a) * RPBW + rw0 + c];
        }
    }

    float mx = -1e30f;
    #pragma unroll
    for (int n = 0; n < KK; n++) mx = fmaxf(mx, p[n]);
    float ssum = 0.0f;
    #pragma unroll
    for (int n = 0; n < KK; n++) { p[n] = __expf(p[n] - mx); ssum += p[n]; }
    const float inv = __fdividef(1.0f, ssum);
    __syncthreads();

    for (int idx = tid; idx < NBR * 4; idx += 128) {
        const int rr = idx >> 2, j = idx & 3;
        const int gh = o_h + rr / NBW, gw = o_w + rr % NBW;
        *(uint4*)&kv_s[rr * KVP + j * 8] =
            *(const uint4*)&vbuf[(size_t)(gh * Wdim + gw) * Cdim + hd * HD + j * 8];
    }
    __syncthreads();

    __half2 acc2[16];
    #pragma unroll
    for (int j = 0; j < 16; j++) acc2[j] = __float2half2_rn(0.f);
    #pragma unroll
    for (int a = 0; a < KW; a++) {
        #pragma unroll
        for (int c = 0; c < KW; c++) {
            const __half2 ph = __float2half2_rn(p[a * KW + c] * inv);
            const uint4* vp = (const uint4*)&kv_s[((lr0 + a) * NBW + lc0 + c) * KVP];
            #pragma unroll
            for (int j = 0; j < 4; j++) {
                uint4 t = vp[j];
                acc2[j*4+0] = __hfma2(ph, *(__half2*)&t.x, acc2[j*4+0]);
                acc2[j*4+1] = __hfma2(ph, *(__half2*)&t.y, acc2[j*4+1]);
                acc2[j*4+2] = __hfma2(ph, *(__half2*)&t.z, acc2[j*4+2]);
                acc2[j*4+3] = __hfma2(ph, *(__half2*)&t.w, acc2[j*4+3]);
            }
        }
    }
    const size_t base = (size_t)(h * Wdim + w) * Cdim + hd * HD;
    #pragma unroll
    for (int j = 0; j < 16; j++)
        *(uint32_t*)&obuf[base + j * 2] = *(uint32_t*)&acc2[j];
}

// ---------------- launch -----------------
extern "C" void kernel_launch(void* const* d_in, const int* in_sizes, int n_in,
                              void* d_out, int out_size)
{
    const float* x      = (const float*)d_in[0];
    const float* y      = (const float*)d_in[1];
    const float* qv_w   = (const float*)d_in[2];
    const float* qv_b   = (const float*)d_in[3];
    const float* k_w    = (const float*)d_in[4];
    const float* k_b    = (const float*)d_in[5];
    const float* rpb    = (const float*)d_in[6];
    const float* proj_w = (const float*)d_in[7];
    const float* proj_b = (const float*)d_in[8];
    const float* n1_w   = (const float*)d_in[9];
    const float* n1_b   = (const float*)d_in[10];
    const float* n2_w   = (const float*)d_in[11];
    const float* n2_b   = (const float*)d_in[12];
    const float* fc1_w  = (const float*)d_in[13];
    const float* fc1_b  = (const float*)d_in[14];
    const float* fc2_w  = (const float*)d_in[15];
    const float* fc2_b  = (const float*)d_in[16];
    float* out = (float*)d_out;

    float* p_x2;
    __half *p_qh, *p_vh, *p_kh, *xn, *yhh, *att, *hb, *wb;
    cudaGetSymbolAddress((void**)&p_x2, g_x2);
    cudaGetSymbolAddress((void**)&p_qh, g_qh);
    cudaGetSymbolAddress((void**)&p_vh, g_vh);
    cudaGetSymbolAddress((void**)&p_kh, g_kh);
    cudaGetSymbolAddress((void**)&xn,  s_xn);
    cudaGetSymbolAddress((void**)&yhh, s_yh);
    cudaGetSymbolAddress((void**)&att, s_att);
    cudaGetSymbolAddress((void**)&hb,  s_h);
    cudaGetSymbolAddress((void**)&wb,  s_w);

    cudaFuncSetAttribute(gemm_qvk,     cudaFuncAttributeMaxDynamicSharedMemorySize, GSMEM2);
    cudaFuncSetAttribute(gemm_proj_ln, cudaFuncAttributeMaxDynamicSharedMemorySize, GSMEM3);
    cudaFuncSetAttribute(gemm_gelu,    cudaFuncAttributeMaxDynamicSharedMemorySize, GSMEM2);
    cudaFuncSetAttribute(gemm_res2,    cudaFuncAttributeMaxDynamicSharedMemorySize, GSMEM);

    // 1) prep: LN1(x) + y->fp16 + w->fp16
    prep_kernel<<<12672, 256>>>(x, n1_w, n1_b, y, qv_w, k_w, proj_w, fc1_w, fc2_w,
                                xn, yhh, wb);

    // 2) fused qv + k GEMMs (n128 tiles; bx=0 q, bx=1 v, bx=2 k)
    gemm_qvk<<<dim3(3, NPIX / 64), 128, GSMEM2>>>(
        xn, yhh, wb, qv_b, k_b, p_qh, p_vh, p_kh);

    // 3) neighborhood attention (half2)
    attn_kernel<<<dim3(Wdim / 16, Hdim / 8, HEADS), 128>>>(p_qh, p_vh, p_kh, rpb, att);

    // 4) proj GEMM (32x128 tiles, grid 512) + residual + fused LN2
    gemm_proj_ln<<<NPIX / 32, 128, GSMEM3>>>(
        att, wb + 49152, proj_b, x, n2_w, n2_b, p_x2, xn);

    // 5) fc1 + GELU (n128 tiles)
    gemm_gelu<<<dim3(4, NPIX / 64), 128, GSMEM2>>>(
        xn, wb + 65536, fc1_b, hb);

    // 6) fc2 + residual -> out
    gemm_res2<<<dim3(2, NPIX / 64), 128, GSMEM>>>(
        hb, wb + 131072, fc2_b, p_x2, out);
}

// round 14
// speedup vs baseline: 1.0028x; 1.0028x over previous
#include <cuda_runtime.h>
#include <cuda_fp16.h>
#include <math.h>
#include <stdint.h>

#define Hdim 128
#define Wdim 128
#define Cdim 128
#define NPIX (Hdim * Wdim)
#define HEADS 4
#define HD 32
#define KW 7
#define KK 49
#define RPBW 13
#define QSCALE 0.17677669529663689f

// ---------------- scratch ----------------
__device__ float  g_x2 [NPIX * Cdim];
__device__ __half g_qh [NPIX * Cdim];
__device__ __half g_vh [NPIX * Cdim];
__device__ __half g_kh [NPIX * Cdim];
__device__ __half s_xn [NPIX * Cdim];
__device__ __half s_yh [NPIX * Cdim];
__device__ __half s_att[NPIX * Cdim];
__device__ __half s_h  [NPIX * 512];
// weights fp16: qv@0 (32768), k@32768, proj@49152, fc1@65536, fc2@131072
__device__ __half s_w  [196608];

// ---------------- helpers ----------------
__device__ __forceinline__ uint32_t smem_u32(const void* p) {
    uint32_t a;
    asm("{ .reg .u64 t; cvta.to.shared.u64 t, %1; cvt.u32.u64 %0, t; }" : "=r"(a) : "l"(p));
    return a;
}
__device__ __forceinline__ void ldm_x4(uint32_t& r0, uint32_t& r1, uint32_t& r2, uint32_t& r3,
                                       uint32_t addr) {
    asm volatile("ldmatrix.sync.aligned.m8n8.x4.shared.b16 {%0,%1,%2,%3}, [%4];"
        : "=r"(r0), "=r"(r1), "=r"(r2), "=r"(r3) : "r"(addr));
}
__device__ __forceinline__ void mma_f16(float* d, const uint32_t* a, const uint32_t* b) {
    asm volatile("mma.sync.aligned.m16n8k16.row.col.f32.f16.f16.f32 "
        "{%0,%1,%2,%3}, {%4,%5,%6,%7}, {%8,%9}, {%0,%1,%2,%3};"
        : "+f"(d[0]), "+f"(d[1]), "+f"(d[2]), "+f"(d[3])
        : "r"(a[0]), "r"(a[1]), "r"(a[2]), "r"(a[3]), "r"(b[0]), "r"(b[1]));
}
__device__ __forceinline__ void cp16(uint32_t dst, const void* src) {
    asm volatile("cp.async.cg.shared.global [%0], [%1], 16;" :: "r"(dst), "l"(src));
}
#define CP_COMMIT() asm volatile("cp.async.commit_group;" ::: "memory")
#define CP_WAIT(n)  asm volatile("cp.async.wait_group %0;" :: "n"(n) : "memory")
__device__ __forceinline__ uint32_t pack_h2(float a, float b) {
    __half2 t = __floats2half2_rn(a, b);
    return *(uint32_t*)&t;
}

// ---------------- prep: LN1 + y->fp16 + w->fp16 ----------------
__global__ void prep_kernel(const float* __restrict__ x,
                            const float* __restrict__ n1w, const float* __restrict__ n1b,
                            const float* __restrict__ y,
                            const float* __restrict__ qvw, const float* __restrict__ kw,
                            const float* __restrict__ pw,  const float* __restrict__ f1,
                            const float* __restrict__ f2,
                            __half* __restrict__ xn, __half* __restrict__ yh,
                            __half* __restrict__ wdst)
{
    const int b = blockIdx.x, tid = threadIdx.x;
    if (b < 8192) {
        const int row = b * 2 + (tid >> 7);
        const int r = tid & 127;
        float v = x[row * Cdim + r];
        float s = v, s2 = v * v;
        #pragma unroll
        for (int o = 16; o; o >>= 1) {
            s  += __shfl_xor_sync(0xffffffffu, s,  o);
            s2 += __shfl_xor_sync(0xffffffffu, s2, o);
        }
        __shared__ float ss[8], ss2[8];
        const int wrp = tid >> 5;
        if ((tid & 31) == 0) { ss[wrp] = s; ss2[wrp] = s2; }
        __syncthreads();
        const int base = (tid >> 7) * 4;
        s  = ss[base]  + ss[base + 1]  + ss[base + 2]  + ss[base + 3];
        s2 = ss2[base] + ss2[base + 1] + ss2[base + 2] + ss2[base + 3];
        float mu  = s * (1.0f / Cdim);
        float var = s2 * (1.0f / Cdim) - mu * mu;
        float rr = (v - mu) * rsqrtf(var + 1e-5f) * n1w[r] + n1b[r];
        xn[row * Cdim + r] = __float2half(rr);
    } else if (b < 12288) {
        const int i = (b - 8192) * 512 + tid * 2;
        yh[i]     = __float2half(y[i]);
        yh[i + 1] = __float2half(y[i + 1]);
    } else {
        const int wi = (b - 12288) * 512 + tid * 2;
        #pragma unroll
        for (int e = 0; e < 2; e++) {
            int q = wi + e;
            if (q < 196608) {
                float v;
                if      (q < 32768)  v = qvw[q];
                else if (q < 49152)  v = kw [q - 32768];
                else if (q < 65536)  v = pw [q - 49152];
                else if (q < 131072) v = f1 [q - 65536];
                else                 v = f2 [q - 131072];
                wdst[q] = __float2half(v);
            }
        }
    }
}

// ---------------- GEMM core 64x64 (fc2) ----------
#define OFF_W  9216
#define STAGE  18432
#define GSMEM  (2 * STAGE)

template <int KTOT>
__device__ __forceinline__ void gemm_core(
    const __half* __restrict__ A, const __half* __restrict__ W,
    int bm, int bn, uint32_t sb, float acc[2][4][4])
{
    const int tid = threadIdx.x, lane = tid & 31, wid = tid >> 5;
    const int wm = wid & 1, wn = wid >> 1;
    const int nch = KTOT / 64;

    #pragma unroll
    for (int i = 0; i < 2; i++)
        #pragma unroll
        for (int j = 0; j < 4; j++)
            #pragma unroll
            for (int q = 0; q < 4; q++) acc[i][j][q] = 0.0f;

    const uint32_t aRow = wm * 32 + (lane & 15);
    const uint32_t aKof = ((lane >> 4) << 3);
    const uint32_t bRow = wn * 32 + ((lane >> 4) << 3) + (lane & 7);
    const uint32_t bKof = ((lane >> 3) & 1) << 3;

    #pragma unroll
    for (int t = tid; t < 1024; t += 128) {
        const int isW = t >> 9;
        const int u = t & 511, row = u >> 3, c8 = u & 7;
        const uint32_t dst = sb + isW * OFF_W + row * 144 + c8 * 16;
        const __half* src = (isW ? W : A) +
            (size_t)((isW ? bn : bm) * 64 + row) * KTOT + c8 * 8;
        cp16(dst, src);
    }
    CP_COMMIT();

    for (int ch = 0; ch < nch; ch++) {
        if (ch + 1 < nch) {
            const uint32_t st = sb + ((ch + 1) & 1) * STAGE;
            const int kb = (ch + 1) * 64;
            #pragma unroll
            for (int t = tid; t < 1024; t += 128) {
                const int isW = t >> 9;
                const int u = t & 511, row = u >> 3, c8 = u & 7;
                const uint32_t dst = st + isW * OFF_W + row * 144 + c8 * 16;
                const __half* src = (isW ? W : A) +
                    (size_t)((isW ? bn : bm) * 64 + row) * KTOT + kb + c8 * 8;
                cp16(dst, src);
            }
            CP_COMMIT();
            CP_WAIT(1);
        } else {
            CP_WAIT(0);
        }
        __syncthreads();

        const uint32_t st = sb + (ch & 1) * STAGE;
        #pragma unroll
        for (int ks = 0; ks < 4; ks++) {
            const uint32_t aoff = st + (aRow * 72 + ks * 16 + aKof) * 2;
            const uint32_t boff = st + OFF_W + (bRow * 72 + ks * 16 + bKof) * 2;
            uint32_t a0[4], a1[4], w0[4], w1[4];
            ldm_x4(a0[0], a0[1], a0[2], a0[3], aoff);
            ldm_x4(a1[0], a1[1], a1[2], a1[3], aoff + 16 * 144);
            ldm_x4(w0[0], w0[1], w0[2], w0[3], boff);
            ldm_x4(w1[0], w1[1], w1[2], w1[3], boff + 16 * 144);

            mma_f16(acc[0][0], a0, w0); mma_f16(acc[0][1], a0, w0 + 2);
            mma_f16(acc[0][2], a0, w1); mma_f16(acc[0][3], a0, w1 + 2);
            mma_f16(acc[1][0], a1, w0); mma_f16(acc[1][1], a1, w0 + 2);
            mma_f16(acc[1][2], a1, w1); mma_f16(acc[1][3], a1, w1 + 2);
        }
        __syncthreads();
    }
}

// ---------------- GEMM core 64x128 (qvk, proj, fc1) ----------
#define OFF_W2 9216
#define STAGE2 27648
#define GSMEM2 (2 * STAGE2)

template <int KTOT>
__device__ __forceinline__ void gemm_core_n128(
    const __half* __restrict__ A, const __half* __restrict__ W,
    int bm, uint32_t sb, float acc[2][8][4])
{
    const int tid = threadIdx.x, lane = tid & 31, wid = tid >> 5;
    const int wm = wid & 1, wn = wid >> 1;
    const int nch = KTOT / 64;

    #pragma unroll
    for (int i = 0; i < 2; i++)
        #pragma unroll
        for (int j = 0; j < 8; j++)
            #pragma unroll
            for (int q = 0; q < 4; q++) acc[i][j][q] = 0.0f;

    const uint32_t aRow = wm * 32 + (lane & 15);
    const uint32_t aKof = ((lane >> 4) << 3);
    const uint32_t bRow = wn * 64 + ((lane >> 4) << 3) + (lane & 7);
    const uint32_t bKof = ((lane >> 3) & 1) << 3;

    #pragma unroll
    for (int t = tid; t < 1536; t += 128) {
        const int isW = t >= 512;
        const int u = isW ? (t - 512) : t;
        const int row = u >> 3, c8 = u & 7;
        const uint32_t dst = sb + (isW ? OFF_W2 : 0) + row * 144 + c8 * 16;
        const __half* src = isW ? (W + (size_t)row * KTOT + c8 * 8)
                                : (A + (size_t)(bm * 64 + row) * KTOT + c8 * 8);
        cp16(dst, src);
    }
    CP_COMMIT();

    for (int ch = 0; ch < nch; ch++) {
        if (ch + 1 < nch) {
            const uint32_t st = sb + ((ch + 1) & 1) * STAGE2;
            const int kb = (ch + 1) * 64;
            #pragma unroll
            for (int t = tid; t < 1536; t += 128) {
                const int isW = t >= 512;
                const int u = isW ? (t - 512) : t;
                const int row = u >> 3, c8 = u & 7;
                const uint32_t dst = st + (isW ? OFF_W2 : 0) + row * 144 + c8 * 16;
                const __half* src = isW ? (W + (size_t)row * KTOT + kb + c8 * 8)
                                        : (A + (size_t)(bm * 64 + row) * KTOT + kb + c8 * 8);
                cp16(dst, src);
            }
            CP_COMMIT();
            CP_WAIT(1);
        } else {
            CP_WAIT(0);
        }
        __syncthreads();

        const uint32_t st = sb + (ch & 1) * STAGE2;
        #pragma unroll
        for (int ks = 0; ks < 4; ks++) {
            const uint32_t aoff = st + (aRow * 72 + ks * 16 + aKof) * 2;
            uint32_t a0[4], a1[4];
            ldm_x4(a0[0], a0[1], a0[2], a0[3], aoff);
            ldm_x4(a1[0], a1[1], a1[2], a1[3], aoff + 16 * 144);
            uint32_t wf[4][4];
            #pragma unroll
            for (int nf4 = 0; nf4 < 4; nf4++) {
                const uint32_t boff = st + OFF_W2 +
                    ((bRow + nf4 * 16) * 72 + ks * 16 + bKof) * 2;
                ldm_x4(wf[nf4][0], wf[nf4][1], wf[nf4][2], wf[nf4][3], boff);
            }
            #pragma unroll
            for (int nf4 = 0; nf4 < 4; nf4++) {
                mma_f16(acc[0][nf4 * 2],     a0, wf[nf4]);
                mma_f16(acc[0][nf4 * 2 + 1], a0, wf[nf4] + 2);
            }
            #pragma unroll
            for (int nf4 = 0; nf4 < 4; nf4++) {
                mma_f16(acc[1][nf4 * 2],     a1, wf[nf4]);
                mma_f16(acc[1][nf4 * 2 + 1], a1, wf[nf4] + 2);
            }
        }
        __syncthreads();
    }
}

// ---------------- fused qv + k GEMM (n128 tiles) ---------------------------
__global__ __launch_bounds__(128, 4)
void gemm_qvk(const __half* __restrict__ xn, const __half* __restrict__ yh,
              const __half* __restrict__ wbuf,
              const float* __restrict__ qv_b, const float* __restrict__ k_b,
              __half* __restrict__ qout,
              __half* __restrict__ vout, __half* __restrict__ kout)
{
    extern __shared__ __align__(16) char dsm[];
    const uint32_t sb = smem_u32(dsm);
    const int bx = blockIdx.x, bm = blockIdx.y;
    float acc[2][8][4];
    const __half* A = (bx == 2) ? yh : xn;
    const __half* W = (bx == 0) ? wbuf : (bx == 1 ? wbuf + 16384 : wbuf + 32768);
    gemm_core_n128<128>(A, W, bm, sb, acc);

    const float* bias = (bx == 0) ? qv_b : (bx == 1 ? qv_b + 128 : k_b);
    __half* outp = (bx == 0) ? qout : (bx == 1 ? vout : kout);
    const float qs = (bx == 0) ? QSCALE : 1.0f;

    const int tid = threadIdx.x, lane = tid & 31, wid = tid >> 5;
    const int wm = wid & 1, wn = wid >> 1;
    #pragma unroll
    for (int mf = 0; mf < 2; mf++) {
        const int row0 = bm * 64 + wm * 32 + mf * 16 + (lane >> 2);
        #pragma unroll
        for (int nf = 0; nf < 8; nf++) {
            const int col = wn * 64 + nf * 8 + (lane & 3) * 2;
            float* a = acc[mf][nf];
            float2 bi = *(const float2*)&bias[col];
            *(uint32_t*)&outp[(size_t)row0 * 128 + col] =
                pack_h2((a[0] + bi.x) * qs, (a[1] + bi.y) * qs);
            *(uint32_t*)&outp[(size_t)(row0 + 8) * 128 + col] =
                pack_h2((a[2] + bi.x) * qs, (a[3] + bi.y) * qs);
        }
    }
}

// ---------------- proj GEMM (64x128) + residual + register-LN2 -------------
__global__ __launch_bounds__(128, 4)
void gemm_proj_ln(const __half* __restrict__ A, const __half* __restrict__ W,
                  const float* __restrict__ bias, const float* __restrict__ res,
                  const float* __restrict__ n2w, const float* __restrict__ n2b,
                  float* __restrict__ x2out, __half* __restrict__ xnout)
{
    extern __shared__ __align__(16) char dsm[];
    const uint32_t sb = smem_u32(dsm);
    const int bm = blockIdx.x;
    float acc[2][8][4];
    gemm_core_n128<128>(A, W, bm, sb, acc);

    const int tid = threadIdx.x, lane = tid & 31, wid = tid >> 5;
    const int wm = wid & 1, wn = wid >> 1;
    float2* part = (float2*)dsm;     // [2 halves][64 rows] partial (s, s2)

    // pass 1: v = acc + bias + res; write x2; fold v back into acc; row partials
    float rs_[2][2], rs2_[2][2];     // [mf][half(0=row0,1=row0+8)]
    #pragma unroll
    for (int mf = 0; mf < 2; mf++) {
        const int lr = wm * 32 + mf * 16 + (lane >> 2);
        const int grow = bm * 64 + lr;
        float s0 = 0.f, s20 = 0.f, s1 = 0.f, s21 = 0.f;
        #pragma unroll
        for (int nf = 0; nf < 8; nf++) {
            const int col = wn * 64 + nf * 8 + (lane & 3) * 2;
            float* a = acc[mf][nf];
            float2 bi = *(const float2*)&bias[col];
            float2 r0 = *(const float2*)&res[(size_t)grow * 128 + col];
            float2 r1 = *(const float2*)&res[(size_t)(grow + 8) * 128 + col];
            float v0 = a[0] + bi.x + r0.x, v1 = a[1] + bi.y + r0.y;
            float v2 = a[2] + bi.x + r1.x, v3 = a[3] + bi.y + r1.y;
            *(float2*)&x2out[(size_t)grow * 128 + col]       = make_float2(v0, v1);
            *(float2*)&x2out[(size_t)(grow + 8) * 128 + col] = make_float2(v2, v3);
            a[0] = v0; a[1] = v1; a[2] = v2; a[3] = v3;
            s0 += v0 + v1; s20 += v0 * v0 + v1 * v1;
            s1 += v2 + v3; s21 += v2 * v2 + v3 * v3;
        }
        // reduce across the 4 threads sharing each row (lane&3 group)
        #pragma unroll
        for (int o = 1; o <= 2; o <<= 1) {
            s0  += __shfl_xor_sync(0xffffffffu, s0,  o);
            s20 += __shfl_xor_sync(0xffffffffu, s20, o);
            s1  += __shfl_xor_sync(0xffffffffu, s1,  o);
            s21 += __shfl_xor_sync(0xffffffffu, s21, o);
        }
        rs_[mf][0] = s0; rs2_[mf][0] = s20;
        rs_[mf][1] = s1; rs2_[mf][1] = s21;
        if ((lane & 3) == 0) {
            part[wn * 64 + lr]     = make_float2(s0, s20);
            part[wn * 64 + lr + 8] = make_float2(s1, s21);
        }
    }
    __syncthreads();

    // pass 2: add other half's partials, normalize from registers, store xn
    #pragma unroll
    for (int mf = 0; mf < 2; mf++) {
        const int lr = wm * 32 + mf * 16 + (lane >> 2);
        const int grow = bm * 64 + lr;
        #pragma unroll
        for (int hh = 0; hh < 2; hh++) {
            float2 oth = part[(1 - wn) * 64 + lr + hh * 8];
            const float s  = rs_[mf][hh]  + oth.x;
            const float s2 = rs2_[mf][hh] + oth.y;
            const float mu  = s * (1.0f / 128.0f);
            const float var = s2 * (1.0f / 128.0f) - mu * mu;
            const float rsq = rsqrtf(var + 1e-5f);
            const int gr = grow + hh * 8;
            #pragma unroll
            for (int nf = 0; nf < 8; nf++) {
                const int col = wn * 64 + nf * 8 + (lane & 3) * 2;
                float2 wv = *(const float2*)&n2w[col];
                float2 bv = *(const float2*)&n2b[col];
                float* a = acc[mf][nf];
                const float va = a[hh * 2], vb = a[hh * 2 + 1];
                *(uint32_t*)&xnout[(size_t)gr * 128 + col] =
                    pack_h2((va - mu) * rsq * wv.x + bv.x,
                            (vb - mu) * rsq * wv.y + bv.y);
            }
        }
    }
}

// ---------------- fc1 (n128 tiles): GEMM + GELU -> fp16 ----------------
__global__ __launch_bounds__(128, 4)
void gemm_gelu(const __half* __restrict__ A, const __half* __restrict__ wbuf,
               const float* __restrict__ bias,
               __half* __restrict__ o)
{
    extern __shared__ __align__(16) char dsm[];
    const uint32_t sb = smem_u32(dsm);
    const int bn = blockIdx.x, bm = blockIdx.y;
    float acc[2][8][4];
    gemm_core_n128<128>(A, wbuf + (size_t)bn * 128 * 128, bm, sb, acc);

    const int tid = threadIdx.x, lane = tid & 31, wid = tid >> 5;
    const int wm = wid & 1, wn = wid >> 1;
    #pragma unroll
    for (int mf = 0; mf < 2; mf++) {
        const int row0 = bm * 64 + wm * 32 + mf * 16 + (lane >> 2);
        #pragma unroll
        for (int nf = 0; nf < 8; nf++) {
            const int col = bn * 128 + wn * 64 + nf * 8 + (lane & 3) * 2;
            float* a = acc[mf][nf];
            float2 bi = *(const float2*)&bias[col];
            float v[4];
            v[0] = a[0] + bi.x; v[1] = a[1] + bi.y;
            v[2] = a[2] + bi.x; v[3] = a[3] + bi.y;
            #pragma unroll
            for (int e = 0; e < 4; e++)
                v[e] = 0.5f * v[e] * (1.0f + erff(v[e] * 0.70710678118654752f));
            *(uint32_t*)&o[(size_t)row0 * 512 + col]       = pack_h2(v[0], v[1]);
            *(uint32_t*)&o[(size_t)(row0 + 8) * 512 + col] = pack_h2(v[2], v[3]);
        }
    }
}

// ---------------- fc2 (64x64, K=512): GEMM + residual -> out ---------------
__global__ __launch_bounds__(128, 5)
void gemm_res2(const __half* __restrict__ A, const __half* __restrict__ W,
               const float* __restrict__ bias, const float* __restrict__ res,
               float* __restrict__ outf)
{
    extern __shared__ __align__(16) char dsm[];
    const uint32_t sb = smem_u32(dsm);
    const int bn = blockIdx.x, bm = blockIdx.y;
    float acc[2][4][4];
    gemm_core<512>(A, W, bm, bn, sb, acc);

    const int tid = threadIdx.x, lane = tid & 31, wid = tid >> 5;
    const int wm = wid & 1, wn = wid >> 1;
    #pragma unroll
    for (int mf = 0; mf < 2; mf++) {
        const int row0 = bm * 64 + wm * 32 + mf * 16 + (lane >> 2);
        #pragma unroll
        for (int nf = 0; nf < 4; nf++) {
            const int col = bn * 64 + wn * 32 + nf * 8 + (lane & 3) * 2;
            float* a = acc[mf][nf];
            float2 bi = *(const float2*)&bias[col];
            float2 r0 = *(const float2*)&res[(size_t)row0 * 128 + col];
            float2 r1 = *(const float2*)&res[(size_t)(row0 + 8) * 128 + col];
            *(float2*)&outf[(size_t)row0 * 128 + col] =
                make_float2(a[0] + bi.x + r0.x, a[1] + bi.y + r0.y);
            *(float2*)&outf[(size_t)(row0 + 8) * 128 + col] =
                make_float2(a[2] + bi.x + r1.x, a[3] + bi.y + r1.y);
        }
    }
}

// ------- neighborhood attention: full half2 arithmetic (proven) --------
#define NBW 22
#define NBH 14
#define NBR (NBW * NBH)
#define KVP 40

__global__ __launch_bounds__(128)
void attn_kernel(const __half* __restrict__ qbuf,
                 const __half* __restrict__ vbuf,
                 const __half* __restrict__ kbuf,
                 const float* __restrict__ rpb,
                 __half* __restrict__ obuf)
{
    __shared__ __align__(16) __half kv_s[NBR * KVP];
    __shared__ float rpb_s[RPBW * RPBW];

    const int hd = blockIdx.z;
    const int bw = blockIdx.x * 16, bh = blockIdx.y * 8;
    const int tid = threadIdx.x;
    const int px = tid & 15, py = tid >> 4;
    const int h = bh + py, w = bw + px;
    const int o_h = min(max(bh - 3, 0), Hdim - NBH);
    const int o_w = min(max(bw - 3, 0), Wdim - NBW);

    for (int i = tid; i < RPBW * RPBW; i += 128) rpb_s[i] = rpb[hd * RPBW * RPBW + i];

    for (int idx = tid; idx < NBR * 4; idx += 128) {
        const int rr = idx >> 2, j = idx & 3;
        const int gh = o_h + rr / NBW, gw = o_w + rr % NBW;
        *(uint4*)&kv_s[rr * KVP + j * 8] =
            *(const uint4*)&kbuf[(size_t)(gh * Wdim + gw) * Cdim + hd * HD + j * 8];
    }
    __syncthreads();

    uint32_t qw[16];
    {
        const uint4* qp = (const uint4*)&qbuf[(size_t)(h * Wdim + w) * Cdim + hd * HD];
        #pragma unroll
        for (int j = 0; j < 4; j++) {
            uint4 t = qp[j];
            qw[j * 4] = t.x; qw[j * 4 + 1] = t.y; qw[j * 4 + 2] = t.z; qw[j * 4 + 3] = t.w;
        }
    }

    const int sh = min(max(h - 3, 0), Hdim - KW);
    const int sw = min(max(w - 3, 0), Wdim - KW);
    const int lr0 = sh - o_h, lc0 = sw - o_w;
    const int rh0 = sh - h + 6, rw0 = sw - w + 6;

    float p[KK];
    #pragma unroll
    for (int a = 0; a < KW; a++) {
        #pragma unroll
        for (int c = 0; c < KW; c++) {
            const uint4* kp = (const uint4*)&kv_s[((lr0 + a) * NBW + lc0 + c) * KVP];
            __half2 d0 = __float2half2_rn(0.f), d1 = d0, d2 = d0, d3 = d0;
            #pragma unroll
            for (int j = 0; j < 4; j++) {
                uint4 t = kp[j];
                d0 = __hfma2(*(__half2*)&qw[j*4+0], *(__half2*)&t.x, d0);
                d1 = __hfma2(*(__half2*)&qw[j*4+1], *(__half2*)&t.y, d1);
                d2 = __hfma2(*(__half2*)&qw[j*4+2], *(__half2*)&t.z, d2);
                d3 = __hfma2(*(__half2*)&qw[j*4+3], *(__half2*)&t.w, d3);
            }
            __half2 ds = __hadd2(__hadd2(d0, d1), __hadd2(d2, d3));
            p[a * KW + c] = __low2float(ds) + __high2float(ds)
                          + rpb_s[(rh0 + a) * RPBW + rw0 + c];
        }
    }

    float mx = -1e30f;
    #pragma unroll
    for (int n = 0; n < KK; n++) mx = fmaxf(mx, p[n]);
    float ssum = 0.0f;
    #pragma unroll
    for (int n = 0; n < KK; n++) { p[n] = __expf(p[n] - mx); ssum += p[n]; }
    const float inv = __fdividef(1.0f, ssum);
    __syncthreads();

    for (int idx = tid; idx < NBR * 4; idx += 128) {
        const int rr = idx >> 2, j = idx & 3;
        const int gh = o_h + rr / NBW, gw = o_w + rr % NBW;
        *(uint4*)&kv_s[rr * KVP + j * 8] =
            *(const uint4*)&vbuf[(size_t)(gh * Wdim + gw) * Cdim + hd * HD + j * 8];
    }
    __syncthreads();

    __half2 acc2[16];
    #pragma unroll
    for (int j = 0; j < 16; j++) acc2[j] = __float2half2_rn(0.f);
    #pragma unroll
    for (int a = 0; a < KW; a++) {
        #pragma unroll
        for (int c = 0; c < KW; c++) {
            const __half2 ph = __float2half2_rn(p[a * KW + c] * inv);
            const uint4* vp = (const uint4*)&kv_s[((lr0 + a) * NBW + lc0 + c) * KVP];
            #pragma unroll
            for (int j = 0; j < 4; j++) {
                uint4 t = vp[j];
                acc2[j*4+0] = __hfma2(ph, *(__half2*)&t.x, acc2[j*4+0]);
                acc2[j*4+1] = __hfma2(ph, *(__half2*)&t.y, acc2[j*4+1]);
                acc2[j*4+2] = __hfma2(ph, *(__half2*)&t.z, acc2[j*4+2]);
                acc2[j*4+3] = __hfma2(ph, *(__half2*)&t.w, acc2[j*4+3]);
            }
        }
    }
    const size_t base = (size_t)(h * Wdim + w) * Cdim + hd * HD;
    #pragma unroll
    for (int j = 0; j < 16; j++)
        *(uint32_t*)&obuf[base + j * 2] = *(uint32_t*)&acc2[j];
}

// ---------------- launch -----------------
extern "C" void kernel_launch(void* const* d_in, const int* in_sizes, int n_in,
                              void* d_out, int out_size)
{
    const float* x      = (const float*)d_in[0];
    const float* y      = (const float*)d_in[1];
    const float* qv_w   = (const float*)d_in[2];
    const float* qv_b   = (const float*)d_in[3];
    const float* k_w    = (const float*)d_in[4];
    const float* k_b    = (const float*)d_in[5];
    const float* rpb    = (const float*)d_in[6];
    const float* proj_w = (const float*)d_in[7];
    const float* proj_b = (const float*)d_in[8];
    const float* n1_w   = (const float*)d_in[9];
    const float* n1_b   = (const float*)d_in[10];
    const float* n2_w   = (const float*)d_in[11];
    const float* n2_b   = (const float*)d_in[12];
    const float* fc1_w  = (const float*)d_in[13];
    const float* fc1_b  = (const float*)d_in[14];
    const float* fc2_w  = (const float*)d_in[15];
    const float* fc2_b  = (const float*)d_in[16];
    float* out = (float*)d_out;

    float* p_x2;
    __half *p_qh, *p_vh, *p_kh, *xn, *yhh, *att, *hb, *wb;
    cudaGetSymbolAddress((void**)&p_x2, g_x2);
    cudaGetSymbolAddress((void**)&p_qh, g_qh);
    cudaGetSymbolAddress((void**)&p_vh, g_vh);
    cudaGetSymbolAddress((void**)&p_kh, g_kh);
    cudaGetSymbolAddress((void**)&xn,  s_xn);
    cudaGetSymbolAddress((void**)&yhh, s_yh);
    cudaGetSymbolAddress((void**)&att, s_att);
    cudaGetSymbolAddress((void**)&hb,  s_h);
    cudaGetSymbolAddress((void**)&wb,  s_w);

    cudaFuncSetAttribute(gemm_qvk,     cudaFuncAttributeMaxDynamicSharedMemorySize, GSMEM2);
    cudaFuncSetAttribute(gemm_proj_ln, cudaFuncAttributeMaxDynamicSharedMemorySize, GSMEM2);
    cudaFuncSetAttribute(gemm_gelu,    cudaFuncAttributeMaxDynamicSharedMemorySize, GSMEM2);
    cudaFuncSetAttribute(gemm_res2,    cudaFuncAttributeMaxDynamicSharedMemorySize, GSMEM);

    // 1) prep: LN1(x) + y->fp16 + w->fp16
    prep_kernel<<<12672, 256>>>(x, n1_w, n1_b, y, qv_w, k_w, proj_w, fc1_w, fc2_w,
                                xn, yhh, wb);

    // 2) fused qv + k GEMMs (n128 tiles; bx=0 q, bx=1 v, bx=2 k)
    gemm_qvk<<<dim3(3, NPIX / 64), 128, GSMEM2>>>(
        xn, yhh, wb, qv_b, k_b, p_qh, p_vh, p_kh);

    // 3) neighborhood attention (half2)
    attn_kernel<<<dim3(Wdim / 16, Hdim / 8, HEADS), 128>>>(p_qh, p_vh, p_kh, rpb, att);

    // 4) proj GEMM (64x128) + residual + register-LN2
    gemm_proj_ln<<<NPIX / 64, 128, GSMEM2>>>(
        att, wb + 49152, proj_b, x, n2_w, n2_b, p_x2, xn);

    // 5) fc1 + GELU (n128 tiles)
    gemm_gelu<<<dim3(4, NPIX / 64), 128, GSMEM2>>>(
        xn, wb + 65536, fc1_b, hb);

    // 6) fc2 + residual -> out
    gemm_res2<<<dim3(2, NPIX / 64), 128, GSMEM>>>(
        hb, wb + 131072, fc2_b, p_x2, out);
}

// round 15
// speedup vs baseline: 1.0294x; 1.0266x over previous
#include <cuda_runtime.h>
#include <cuda_fp16.h>
#include <math.h>
#include <stdint.h>

#define Hdim 128
#define Wdim 128
#define Cdim 128
#define NPIX (Hdim * Wdim)
#define HEADS 4
#define HD 32
#define KW 7
#define KK 49
#define RPBW 13
#define QSCALE 0.17677669529663689f

// ---------------- scratch ----------------
__device__ float  g_x2 [NPIX * Cdim];
__device__ __half g_qh [NPIX * Cdim];
__device__ __half g_vh [NPIX * Cdim];
__device__ __half g_kh [NPIX * Cdim];
__device__ __half s_xn [NPIX * Cdim];
__device__ __half s_yh [NPIX * Cdim];
__device__ __half s_att[NPIX * Cdim];
__device__ __half s_h  [NPIX * 512];
// weights fp16: qv@0 (32768), k@32768, proj@49152, fc1@65536, fc2@131072
__device__ __half s_w  [196608];

// ---------------- helpers ----------------
__device__ __forceinline__ uint32_t smem_u32(const void* p) {
    uint32_t a;
    asm("{ .reg .u64 t; cvta.to.shared.u64 t, %1; cvt.u32.u64 %0, t; }" : "=r"(a) : "l"(p));
    return a;
}
__device__ __forceinline__ void ldm_x4(uint32_t& r0, uint32_t& r1, uint32_t& r2, uint32_t& r3,
                                       uint32_t addr) {
    asm volatile("ldmatrix.sync.aligned.m8n8.x4.shared.b16 {%0,%1,%2,%3}, [%4];"
        : "=r"(r0), "=r"(r1), "=r"(r2), "=r"(r3) : "r"(addr));
}
__device__ __forceinline__ void mma_f16(float* d, const uint32_t* a, const uint32_t* b) {
    asm volatile("mma.sync.aligned.m16n8k16.row.col.f32.f16.f16.f32 "
        "{%0,%1,%2,%3}, {%4,%5,%6,%7}, {%8,%9}, {%0,%1,%2,%3};"
        : "+f"(d[0]), "+f"(d[1]), "+f"(d[2]), "+f"(d[3])
        : "r"(a[0]), "r"(a[1]), "r"(a[2]), "r"(a[3]), "r"(b[0]), "r"(b[1]));
}
__device__ __forceinline__ void cp16(uint32_t dst, const void* src) {
    asm volatile("cp.async.ca.shared.global [%0], [%1], 16;" :: "r"(dst), "l"(src));
}
#define CP_COMMIT() asm volatile("cp.async.commit_group;" ::: "memory")
#define CP_WAIT(n)  asm volatile("cp.async.wait_group %0;" :: "n"(n) : "memory")
__device__ __forceinline__ uint32_t pack_h2(float a, float b) {
    __half2 t = __floats2half2_rn(a, b);
    return *(uint32_t*)&t;
}

// ---------------- prep: LN1 + y->fp16 + w->fp16 ----------------
__global__ void prep_kernel(const float* __restrict__ x,
                            const float* __restrict__ n1w, const float* __restrict__ n1b,
                            const float* __restrict__ y,
                            const float* __restrict__ qvw, const float* __restrict__ kw,
                            const float* __restrict__ pw,  const float* __restrict__ f1,
                            const float* __restrict__ f2,
                            __half* __restrict__ xn, __half* __restrict__ yh,
                            __half* __restrict__ wdst)
{
    const int b = blockIdx.x, tid = threadIdx.x;
    if (b < 8192) {
        const int row = b * 2 + (tid >> 7);
        const int r = tid & 127;
        float v = x[row * Cdim + r];
        float s = v, s2 = v * v;
        #pragma unroll
        for (int o = 16; o; o >>= 1) {
            s  += __shfl_xor_sync(0xffffffffu, s,  o);
            s2 += __shfl_xor_sync(0xffffffffu, s2, o);
        }
        __shared__ float ss[8], ss2[8];
        const int wrp = tid >> 5;
        if ((tid & 31) == 0) { ss[wrp] = s; ss2[wrp] = s2; }
        __syncthreads();
        const int base = (tid >> 7) * 4;
        s  = ss[base]  + ss[base + 1]  + ss[base + 2]  + ss[base + 3];
        s2 = ss2[base] + ss2[base + 1] + ss2[base + 2] + ss2[base + 3];
        float mu  = s * (1.0f / Cdim);
        float var = s2 * (1.0f / Cdim) - mu * mu;
        float rr = (v - mu) * rsqrtf(var + 1e-5f) * n1w[r] + n1b[r];
        xn[row * Cdim + r] = __float2half(rr);
    } else if (b < 12288) {
        const int i = (b - 8192) * 512 + tid * 2;
        yh[i]     = __float2half(y[i]);
        yh[i + 1] = __float2half(y[i + 1]);
    } else {
        const int wi = (b - 12288) * 512 + tid * 2;
        #pragma unroll
        for (int e = 0; e < 2; e++) {
            int q = wi + e;
            if (q < 196608) {
                float v;
                if      (q < 32768)  v = qvw[q];
                else if (q < 49152)  v = kw [q - 32768];
                else if (q < 65536)  v = pw [q - 49152];
                else if (q < 131072) v = f1 [q - 65536];
                else                 v = f2 [q - 131072];
                wdst[q] = __float2half(v);
            }
        }
    }
}

// ---------------- GEMM core 64x64 (fc2) ----------
#define OFF_W  9216
#define STAGE  18432
#define GSMEM  (2 * STAGE)

template <int KTOT>
__device__ __forceinline__ void gemm_core(
    const __half* __restrict__ A, const __half* __restrict__ W,
    int bm, int bn, uint32_t sb, float acc[2][4][4])
{
    const int tid = threadIdx.x, lane = tid & 31, wid = tid >> 5;
    const int wm = wid & 1, wn = wid >> 1;
    const int nch = KTOT / 64;

    #pragma unroll
    for (int i = 0; i < 2; i++)
        #pragma unroll
        for (int j = 0; j < 4; j++)
            #pragma unroll
            for (int q = 0; q < 4; q++) acc[i][j][q] = 0.0f;

    const uint32_t aRow = wm * 32 + (lane & 15);
    const uint32_t aKof = ((lane >> 4) << 3);
    const uint32_t bRow = wn * 32 + ((lane >> 4) << 3) + (lane & 7);
    const uint32_t bKof = ((lane >> 3) & 1) << 3;

    #pragma unroll
    for (int t = tid; t < 1024; t += 128) {
        const int isW = t >> 9;
        const int u = t & 511, row = u >> 3, c8 = u & 7;
        const uint32_t dst = sb + isW * OFF_W + row * 144 + c8 * 16;
        const __half* src = (isW ? W : A) +
            (size_t)((isW ? bn : bm) * 64 + row) * KTOT + c8 * 8;
        cp16(dst, src);
    }
    CP_COMMIT();

    for (int ch = 0; ch < nch; ch++) {
        if (ch + 1 < nch) {
            const uint32_t st = sb + ((ch + 1) & 1) * STAGE;
            const int kb = (ch + 1) * 64;
            #pragma unroll
            for (int t = tid; t < 1024; t += 128) {
                const int isW = t >> 9;
                const int u = t & 511, row = u >> 3, c8 = u & 7;
                const uint32_t dst = st + isW * OFF_W + row * 144 + c8 * 16;
                const __half* src = (isW ? W : A) +
                    (size_t)((isW ? bn : bm) * 64 + row) * KTOT + kb + c8 * 8;
                cp16(dst, src);
            }
            CP_COMMIT();
            CP_WAIT(1);
        } else {
            CP_WAIT(0);
        }
        __syncthreads();

        const uint32_t st = sb + (ch & 1) * STAGE;
        #pragma unroll
        for (int ks = 0; ks < 4; ks++) {
            const uint32_t aoff = st + (aRow * 72 + ks * 16 + aKof) * 2;
            const uint32_t boff = st + OFF_W + (bRow * 72 + ks * 16 + bKof) * 2;
            uint32_t a0[4], a1[4], w0[4], w1[4];
            ldm_x4(a0[0], a0[1], a0[2], a0[3], aoff);
            ldm_x4(a1[0], a1[1], a1[2], a1[3], aoff + 16 * 144);
            ldm_x4(w0[0], w0[1], w0[2], w0[3], boff);
            ldm_x4(w1[0], w1[1], w1[2], w1[3], boff + 16 * 144);

            mma_f16(acc[0][0], a0, w0); mma_f16(acc[0][1], a0, w0 + 2);
            mma_f16(acc[0][2], a0, w1); mma_f16(acc[0][3], a0, w1 + 2);
            mma_f16(acc[1][0], a1, w0); mma_f16(acc[1][1], a1, w0 + 2);
            mma_f16(acc[1][2], a1, w1); mma_f16(acc[1][3], a1, w1 + 2);
        }
        __syncthreads();
    }
}

// ---------------- GEMM core 64x128 (qvk, proj, fc1) ----------
#define OFF_W2 9216
#define STAGE2 27648
#define GSMEM2 (2 * STAGE2)

template <int KTOT>
__device__ __forceinline__ void gemm_core_n128(
    const __half* __restrict__ A, const __half* __restrict__ W,
    int bm, uint32_t sb, float acc[2][8][4])
{
    const int tid = threadIdx.x, lane = tid & 31, wid = tid >> 5;
    const int wm = wid & 1, wn = wid >> 1;
    const int nch = KTOT / 64;

    #pragma unroll
    for (int i = 0; i < 2; i++)
        #pragma unroll
        for (int j = 0; j < 8; j++)
            #pragma unroll
            for (int q = 0; q < 4; q++) acc[i][j][q] = 0.0f;

    const uint32_t aRow = wm * 32 + (lane & 15);
    const uint32_t aKof = ((lane >> 4) << 3);
    const uint32_t bRow = wn * 64 + ((lane >> 4) << 3) + (lane & 7);
    const uint32_t bKof = ((lane >> 3) & 1) << 3;

    #pragma unroll
    for (int t = tid; t < 1536; t += 128) {
        const int isW = t >= 512;
        const int u = isW ? (t - 512) : t;
        const int row = u >> 3, c8 = u & 7;
        const uint32_t dst = sb + (isW ? OFF_W2 : 0) + row * 144 + c8 * 16;
        const __half* src = isW ? (W + (size_t)row * KTOT + c8 * 8)
                                : (A + (size_t)(bm * 64 + row) * KTOT + c8 * 8);
        cp16(dst, src);
    }
    CP_COMMIT();

    for (int ch = 0; ch < nch; ch++) {
        if (ch + 1 < nch) {
            const uint32_t st = sb + ((ch + 1) & 1) * STAGE2;
            const int kb = (ch + 1) * 64;
            #pragma unroll
            for (int t = tid; t < 1536; t += 128) {
                const int isW = t >= 512;
                const int u = isW ? (t - 512) : t;
                const int row = u >> 3, c8 = u & 7;
                const uint32_t dst = st + (isW ? OFF_W2 : 0) + row * 144 + c8 * 16;
                const __half* src = isW ? (W + (size_t)row * KTOT + kb + c8 * 8)
                                        : (A + (size_t)(bm * 64 + row) * KTOT + kb + c8 * 8);
                cp16(dst, src);
            }
            CP_COMMIT();
            CP_WAIT(1);
        } else {
            CP_WAIT(0);
        }
        __syncthreads();

        const uint32_t st = sb + (ch & 1) * STAGE2;
        #pragma unroll
        for (int ks = 0; ks < 4; ks++) {
            const uint32_t aoff = st + (aRow * 72 + ks * 16 + aKof) * 2;
            uint32_t a0[4], a1[4];
            ldm_x4(a0[0], a0[1], a0[2], a0[3], aoff);
            ldm_x4(a1[0], a1[1], a1[2], a1[3], aoff + 16 * 144);
            uint32_t wf[4][4];
            #pragma unroll
            for (int nf4 = 0; nf4 < 4; nf4++) {
                const uint32_t boff = st + OFF_W2 +
                    ((bRow + nf4 * 16) * 72 + ks * 16 + bKof) * 2;
                ldm_x4(wf[nf4][0], wf[nf4][1], wf[nf4][2], wf[nf4][3], boff);
            }
            #pragma unroll
            for (int nf4 = 0; nf4 < 4; nf4++) {
                mma_f16(acc[0][nf4 * 2],     a0, wf[nf4]);
                mma_f16(acc[0][nf4 * 2 + 1], a0, wf[nf4] + 2);
            }
            #pragma unroll
            for (int nf4 = 0; nf4 < 4; nf4++) {
                mma_f16(acc[1][nf4 * 2],     a1, wf[nf4]);
                mma_f16(acc[1][nf4 * 2 + 1], a1, wf[nf4] + 2);
            }
        }
        __syncthreads();
    }
}

// ---------------- fused qv + k GEMM (n128 tiles) ---------------------------
__global__ __launch_bounds__(128, 4)
void gemm_qvk(const __half* __restrict__ xn, const __half* __restrict__ yh,
              const __half* __restrict__ wbuf,
              const float* __restrict__ qv_b, const float* __restrict__ k_b,
              __half* __restrict__ qout,
              __half* __restrict__ vout, __half* __restrict__ kout)
{
    extern __shared__ __align__(16) char dsm[];
    const uint32_t sb = smem_u32(dsm);
    const int bx = blockIdx.x, bm = blockIdx.y;
    float acc[2][8][4];
    const __half* A = (bx == 2) ? yh : xn;
    const __half* W = (bx == 0) ? wbuf : (bx == 1 ? wbuf + 16384 : wbuf + 32768);
    gemm_core_n128<128>(A, W, bm, sb, acc);

    const float* bias = (bx == 0) ? qv_b : (bx == 1 ? qv_b + 128 : k_b);
    __half* outp = (bx == 0) ? qout : (bx == 1 ? vout : kout);
    const float qs = (bx == 0) ? QSCALE : 1.0f;

    const int tid = threadIdx.x, lane = tid & 31, wid = tid >> 5;
    const int wm = wid & 1, wn = wid >> 1;
    #pragma unroll
    for (int mf = 0; mf < 2; mf++) {
        const int row0 = bm * 64 + wm * 32 + mf * 16 + (lane >> 2);
        #pragma unroll
        for (int nf = 0; nf < 8; nf++) {
            const int col = wn * 64 + nf * 8 + (lane & 3) * 2;
            float* a = acc[mf][nf];
            float2 bi = *(const float2*)&bias[col];
            *(uint32_t*)&outp[(size_t)row0 * 128 + col] =
                pack_h2((a[0] + bi.x) * qs, (a[1] + bi.y) * qs);
            *(uint32_t*)&outp[(size_t)(row0 + 8) * 128 + col] =
                pack_h2((a[2] + bi.x) * qs, (a[3] + bi.y) * qs);
        }
    }
}

// ---------------- proj GEMM (64x128) + residual + register-LN2 -------------
__global__ __launch_bounds__(128, 4)
void gemm_proj_ln(const __half* __restrict__ A, const __half* __restrict__ W,
                  const float* __restrict__ bias, const float* __restrict__ res,
                  const float* __restrict__ n2w, const float* __restrict__ n2b,
                  float* __restrict__ x2out, __half* __restrict__ xnout)
{
    extern __shared__ __align__(16) char dsm[];
    const uint32_t sb = smem_u32(dsm);
    const int bm = blockIdx.x;
    float acc[2][8][4];
    gemm_core_n128<128>(A, W, bm, sb, acc);

    const int tid = threadIdx.x, lane = tid & 31, wid = tid >> 5;
    const int wm = wid & 1, wn = wid >> 1;
    float2* part = (float2*)dsm;     // [2 halves][64 rows] partial (s, s2)

    float rs_[2][2], rs2_[2][2];
    #pragma unroll
    for (int mf = 0; mf < 2; mf++) {
        const int lr = wm * 32 + mf * 16 + (lane >> 2);
        const int grow = bm * 64 + lr;
        float s0 = 0.f, s20 = 0.f, s1 = 0.f, s21 = 0.f;
        #pragma unroll
        for (int nf = 0; nf < 8; nf++) {
            const int col = wn * 64 + nf * 8 + (lane & 3) * 2;
            float* a = acc[mf][nf];
            float2 bi = *(const float2*)&bias[col];
            float2 r0 = *(const float2*)&res[(size_t)grow * 128 + col];
            float2 r1 = *(const float2*)&res[(size_t)(grow + 8) * 128 + col];
            float v0 = a[0] + bi.x + r0.x, v1 = a[1] + bi.y + r0.y;
            float v2 = a[2] + bi.x + r1.x, v3 = a[3] + bi.y + r1.y;
            *(float2*)&x2out[(size_t)grow * 128 + col]       = make_float2(v0, v1);
            *(float2*)&x2out[(size_t)(grow + 8) * 128 + col] = make_float2(v2, v3);
            a[0] = v0; a[1] = v1; a[2] = v2; a[3] = v3;
            s0 += v0 + v1; s20 += v0 * v0 + v1 * v1;
            s1 += v2 + v3; s21 += v2 * v2 + v3 * v3;
        }
        #pragma unroll
        for (int o = 1; o <= 2; o <<= 1) {
            s0  += __shfl_xor_sync(0xffffffffu, s0,  o);
            s20 += __shfl_xor_sync(0xffffffffu, s20, o);
            s1  += __shfl_xor_sync(0xffffffffu, s1,  o);
            s21 += __shfl_xor_sync(0xffffffffu, s21, o);
        }
        rs_[mf][0] = s0; rs2_[mf][0] = s20;
        rs_[mf][1] = s1; rs2_[mf][1] = s21;
        if ((lane & 3) == 0) {
            part[wn * 64 + lr]     = make_float2(s0, s20);
            part[wn * 64 + lr + 8] = make_float2(s1, s21);
        }
    }
    __syncthreads();

    #pragma unroll
    for (int mf = 0; mf < 2; mf++) {
        const int lr = wm * 32 + mf * 16 + (lane >> 2);
        const int grow = bm * 64 + lr;
        #pragma unroll
        for (int hh = 0; hh < 2; hh++) {
            float2 oth = part[(1 - wn) * 64 + lr + hh * 8];
            const float s  = rs_[mf][hh]  + oth.x;
            const float s2 = rs2_[mf][hh] + oth.y;
            const float mu  = s * (1.0f / 128.0f);
            const float var = s2 * (1.0f / 128.0f) - mu * mu;
            const float rsq = rsqrtf(var + 1e-5f);
            const int gr = grow + hh * 8;
            #pragma unroll
            for (int nf = 0; nf < 8; nf++) {
                const int col = wn * 64 + nf * 8 + (lane & 3) * 2;
                float2 wv = *(const float2*)&n2w[col];
                float2 bv = *(const float2*)&n2b[col];
                float* a = acc[mf][nf];
                const float va = a[hh * 2], vb = a[hh * 2 + 1];
                *(uint32_t*)&xnout[(size_t)gr * 128 + col] =
                    pack_h2((va - mu) * rsq * wv.x + bv.x,
                            (vb - mu) * rsq * wv.y + bv.y);
            }
        }
    }
}

// ---------------- fc1 (n128 tiles): GEMM + GELU -> fp16 ----------------
__global__ __launch_bounds__(128, 4)
void gemm_gelu(const __half* __restrict__ A, const __half* __restrict__ wbuf,
               const float* __restrict__ bias,
               __half* __restrict__ o)
{
    extern __shared__ __align__(16) char dsm[];
    const uint32_t sb = smem_u32(dsm);
    const int bn = blockIdx.x, bm = blockIdx.y;
    float acc[2][8][4];
    gemm_core_n128<128>(A, wbuf + (size_t)bn * 128 * 128, bm, sb, acc);

    const int tid = threadIdx.x, lane = tid & 31, wid = tid >> 5;
    const int wm = wid & 1, wn = wid >> 1;
    #pragma unroll
    for (int mf = 0; mf < 2; mf++) {
        const int row0 = bm * 64 + wm * 32 + mf * 16 + (lane >> 2);
        #pragma unroll
        for (int nf = 0; nf < 8; nf++) {
            const int col = bn * 128 + wn * 64 + nf * 8 + (lane & 3) * 2;
            float* a = acc[mf][nf];
            float2 bi = *(const float2*)&bias[col];
            float v[4];
            v[0] = a[0] + bi.x; v[1] = a[1] + bi.y;
            v[2] = a[2] + bi.x; v[3] = a[3] + bi.y;
            #pragma unroll
            for (int e = 0; e < 4; e++)
                v[e] = 0.5f * v[e] * (1.0f + erff(v[e] * 0.70710678118654752f));
            *(uint32_t*)&o[(size_t)row0 * 512 + col]       = pack_h2(v[0], v[1]);
            *(uint32_t*)&o[(size_t)(row0 + 8) * 512 + col] = pack_h2(v[2], v[3]);
        }
    }
}

// ---------------- fc2 (64x64, K=512): GEMM + residual -> out ---------------
__global__ __launch_bounds__(128, 5)
void gemm_res2(const __half* __restrict__ A, const __half* __restrict__ W,
               const float* __restrict__ bias, const float* __restrict__ res,
               float* __restrict__ outf)
{
    extern __shared__ __align__(16) char dsm[];
    const uint32_t sb = smem_u32(dsm);
    const int bn = blockIdx.x, bm = blockIdx.y;
    float acc[2][4][4];
    gemm_core<512>(A, W, bm, bn, sb, acc);

    const int tid = threadIdx.x, lane = tid & 31, wid = tid >> 5;
    const int wm = wid & 1, wn = wid >> 1;
    #pragma unroll
    for (int mf = 0; mf < 2; mf++) {
        const int row0 = bm * 64 + wm * 32 + mf * 16 + (lane >> 2);
        #pragma unroll
        for (int nf = 0; nf < 4; nf++) {
            const int col = bn * 64 + wn * 32 + nf * 8 + (lane & 3) * 2;
            float* a = acc[mf][nf];
            float2 bi = *(const float2*)&bias[col];
            float2 r0 = *(const float2*)&res[(size_t)row0 * 128 + col];
            float2 r1 = *(const float2*)&res[(size_t)(row0 + 8) * 128 + col];
            *(float2*)&outf[(size_t)row0 * 128 + col] =
                make_float2(a[0] + bi.x + r0.x, a[1] + bi.y + r0.y);
            *(float2*)&outf[(size_t)(row0 + 8) * 128 + col] =
                make_float2(a[2] + bi.x + r1.x, a[3] + bi.y + r1.y);
        }
    }
}

// ------- neighborhood attention: full half2 arithmetic (proven) --------
#define NBW 22
#define NBH 14
#define NBR (NBW * NBH)
#define KVP 40

__global__ __launch_bounds__(128)
void attn_kernel(const __half* __restrict__ qbuf,
                 const __half* __restrict__ vbuf,
                 const __half* __restrict__ kbuf,
                 const float* __restrict__ rpb,
                 __half* __restrict__ obuf)
{
    __shared__ __align__(16) __half kv_s[NBR * KVP];
    __shared__ float rpb_s[RPBW * RPBW];

    const int hd = blockIdx.z;
    const int bw = blockIdx.x * 16, bh = blockIdx.y * 8;
    const int tid = threadIdx.x;
    const int px = tid & 15, py = tid >> 4;
    const int h = bh + py, w = bw + px;
    const int o_h = min(max(bh - 3, 0), Hdim - NBH);
    const int o_w = min(max(bw - 3, 0), Wdim - NBW);

    for (int i = tid; i < RPBW * RPBW; i += 128) rpb_s[i] = rpb[hd * RPBW * RPBW + i];

    for (int idx = tid; idx < NBR * 4; idx += 128) {
        const int rr = idx >> 2, j = idx & 3;
        const int gh = o_h + rr / NBW, gw = o_w + rr % NBW;
        *(uint4*)&kv_s[rr * KVP + j * 8] =
            *(const uint4*)&kbuf[(size_t)(gh * Wdim + gw) * Cdim + hd * HD + j * 8];
    }
    __syncthreads();

    uint32_t qw[16];
    {
        const uint4* qp = (const uint4*)&qbuf[(size_t)(h * Wdim + w) * Cdim + hd * HD];
        #pragma unroll
        for (int j = 0; j < 4; j++) {
            uint4 t = qp[j];
            qw[j * 4] = t.x; qw[j * 4 + 1] = t.y; qw[j * 4 + 2] = t.z; qw[j * 4 + 3] = t.w;
        }
    }

    const int sh = min(max(h - 3, 0), Hdim - KW);
    const int sw = min(max(w - 3, 0), Wdim - KW);
    const int lr0 = sh - o_h, lc0 = sw - o_w;
    const int rh0 = sh - h + 6, rw0 = sw - w + 6;

    float p[KK];
    #pragma unroll
    for (int a = 0; a < KW; a++) {
        #pragma unroll
        for (int c = 0; c < KW; c++) {
            const uint4* kp = (const uint4*)&kv_s[((lr0 + a) * NBW + lc0 + c) * KVP];
            __half2 d0 = __float2half2_rn(0.f), d1 = d0, d2 = d0, d3 = d0;
            #pragma unroll
            for (int j = 0; j < 4; j++) {
                uint4 t = kp[j];
                d0 = __hfma2(*(__half2*)&qw[j*4+0], *(__half2*)&t.x, d0);
                d1 = __hfma2(*(__half2*)&qw[j*4+1], *(__half2*)&t.y, d1);
                d2 = __hfma2(*(__half2*)&qw[j*4+2], *(__half2*)&t.z, d2);
                d3 = __hfma2(*(__half2*)&qw[j*4+3], *(__half2*)&t.w, d3);
            }
            __half2 ds = __hadd2(__hadd2(d0, d1), __hadd2(d2, d3));
            p[a * KW + c] = __low2float(ds) + __high2float(ds)
                          + rpb_s[(rh0 + a) * RPBW + rw0 + c];
        }
    }

    float mx = -1e30f;
    #pragma unroll
    for (int n = 0; n < KK; n++) mx = fmaxf(mx, p[n]);
    float ssum = 0.0f;
    #pragma unroll
    for (int n = 0; n < KK; n++) { p[n] = __expf(p[n] - mx); ssum += p[n]; }
    const float inv = __fdividef(1.0f, ssum);
    __syncthreads();

    for (int idx = tid; idx < NBR * 4; idx += 128) {
        const int rr = idx >> 2, j = idx & 3;
        const int gh = o_h + rr / NBW, gw = o_w + rr % NBW;
        *(uint4*)&kv_s[rr * KVP + j * 8] =
            *(const uint4*)&vbuf[(size_t)(gh * Wdim + gw) * Cdim + hd * HD + j * 8];
    }
    __syncthreads();

    __half2 acc2[16];
    #pragma unroll
    for (int j = 0; j < 16; j++) acc2[j] = __float2half2_rn(0.f);
    #pragma unroll
    for (int a = 0; a < KW; a++) {
        #pragma unroll
        for (int c = 0; c < KW; c++) {
            const __half2 ph = __float2half2_rn(p[a * KW + c] * inv);
            const uint4* vp = (const uint4*)&kv_s[((lr0 + a) * NBW + lc0 + c) * KVP];
            #pragma unroll
            for (int j = 0; j < 4; j++) {
                uint4 t = vp[j];
                acc2[j*4+0] = __hfma2(ph, *(__half2*)&t.x, acc2[j*4+0]);
                acc2[j*4+1] = __hfma2(ph, *(__half2*)&t.y, acc2[j*4+1]);
                acc2[j*4+2] = __hfma2(ph, *(__half2*)&t.z, acc2[j*4+2]);
                acc2[j*4+3] = __hfma2(ph, *(__half2*)&t.w, acc2[j*4+3]);
            }
        }
    }
    const size_t base = (size_t)(h * Wdim + w) * Cdim + hd * HD;
    #pragma unroll
    for (int j = 0; j < 16; j++)
        *(uint32_t*)&obuf[base + j * 2] = *(uint32_t*)&acc2[j];
}

// ---------------- launch -----------------
extern "C" void kernel_launch(void* const* d_in, const int* in_sizes, int n_in,
                              void* d_out, int out_size)
{
    const float* x      = (const float*)d_in[0];
    const float* y      = (const float*)d_in[1];
    const float* qv_w   = (const float*)d_in[2];
    const float* qv_b   = (const float*)d_in[3];
    const float* k_w    = (const float*)d_in[4];
    const float* k_b    = (const float*)d_in[5];
    const float* rpb    = (const float*)d_in[6];
    const float* proj_w = (const float*)d_in[7];
    const float* proj_b = (const float*)d_in[8];
    const float* n1_w   = (const float*)d_in[9];
    const float* n1_b   = (const float*)d_in[10];
    const float* n2_w   = (const float*)d_in[11];
    const float* n2_b   = (const float*)d_in[12];
    const float* fc1_w  = (const float*)d_in[13];
    const float* fc1_b  = (const float*)d_in[14];
    const float* fc2_w  = (const float*)d_in[15];
    const float* fc2_b  = (const float*)d_in[16];
    float* out = (float*)d_out;

    float* p_x2;
    __half *p_qh, *p_vh, *p_kh, *xn, *yhh, *att, *hb, *wb;
    cudaGetSymbolAddress((void**)&p_x2, g_x2);
    cudaGetSymbolAddress((void**)&p_qh, g_qh);
    cudaGetSymbolAddress((void**)&p_vh, g_vh);
    cudaGetSymbolAddress((void**)&p_kh, g_kh);
    cudaGetSymbolAddress((void**)&xn,  s_xn);
    cudaGetSymbolAddress((void**)&yhh, s_yh);
    cudaGetSymbolAddress((void**)&att, s_att);
    cudaGetSymbolAddress((void**)&hb,  s_h);
    cudaGetSymbolAddress((void**)&wb,  s_w);

    cudaFuncSetAttribute(gemm_qvk,     cudaFuncAttributeMaxDynamicSharedMemorySize, GSMEM2);
    cudaFuncSetAttribute(gemm_proj_ln, cudaFuncAttributeMaxDynamicSharedMemorySize, GSMEM2);
    cudaFuncSetAttribute(gemm_gelu,    cudaFuncAttributeMaxDynamicSharedMemorySize, GSMEM2);
    cudaFuncSetAttribute(gemm_res2,    cudaFuncAttributeMaxDynamicSharedMemorySize, GSMEM);

    // 1) prep: LN1(x) + y->fp16 + w->fp16
    prep_kernel<<<12672, 256>>>(x, n1_w, n1_b, y, qv_w, k_w, proj_w, fc1_w, fc2_w,
                                xn, yhh, wb);

    // 2) fused qv + k GEMMs (n128 tiles; bx=0 q, bx=1 v, bx=2 k)
    gemm_qvk<<<dim3(3, NPIX / 64), 128, GSMEM2>>>(
        xn, yhh, wb, qv_b, k_b, p_qh, p_vh, p_kh);

    // 3) neighborhood attention (half2)
    attn_kernel<<<dim3(Wdim / 16, Hdim / 8, HEADS), 128>>>(p_qh, p_vh, p_kh, rpb, att);

    // 4) proj GEMM (64x128) + residual + register-LN2
    gemm_proj_ln<<<NPIX / 64, 128, GSMEM2>>>(
        att, wb + 49152, proj_b, x, n2_w, n2_b, p_x2, xn);

    // 5) fc1 + GELU (n128 tiles)
    gemm_gelu<<<dim3(4, NPIX / 64), 128, GSMEM2>>>(
        xn, wb + 65536, fc1_b, hb);

    // 6) fc2 + residual -> out
    gemm_res2<<<dim3(2, NPIX / 64), 128, GSMEM>>>(
        hb, wb + 131072, fc2_b, p_x2, out);
}

// round 16
// speedup vs baseline: 1.0491x; 1.0191x over previous
#include <cuda_runtime.h>
#include <cuda_fp16.h>
#include <math.h>
#include <stdint.h>

#define Hdim 128
#define Wdim 128
#define Cdim 128
#define NPIX (Hdim * Wdim)
#define HEADS 4
#define HD 32
#define KW 7
#define KK 49
#define RPBW 13
#define QSCALE 0.17677669529663689f

// ---------------- scratch ----------------
__device__ float  g_x2 [NPIX * Cdim];
__device__ __half g_qh [NPIX * Cdim];
__device__ __half g_vh [NPIX * Cdim];
__device__ __half g_kh [NPIX * Cdim];
__device__ __half s_xn [NPIX * Cdim];
__device__ __half s_yh [NPIX * Cdim];
__device__ __half s_att[NPIX * Cdim];
__device__ __half s_h  [NPIX * 512];
// weights fp16: qv@0 (32768), k@32768, proj@49152, fc1@65536, fc2@131072
__device__ __half s_w  [196608];

// ---------------- helpers ----------------
__device__ __forceinline__ uint32_t smem_u32(const void* p) {
    uint32_t a;
    asm("{ .reg .u64 t; cvta.to.shared.u64 t, %1; cvt.u32.u64 %0, t; }" : "=r"(a) : "l"(p));
    return a;
}
__device__ __forceinline__ void ldm_x4(uint32_t& r0, uint32_t& r1, uint32_t& r2, uint32_t& r3,
                                       uint32_t addr) {
    asm volatile("ldmatrix.sync.aligned.m8n8.x4.shared.b16 {%0,%1,%2,%3}, [%4];"
        : "=r"(r0), "=r"(r1), "=r"(r2), "=r"(r3) : "r"(addr));
}
__device__ __forceinline__ void mma_f16(float* d, const uint32_t* a, const uint32_t* b) {
    asm volatile("mma.sync.aligned.m16n8k16.row.col.f32.f16.f16.f32 "
        "{%0,%1,%2,%3}, {%4,%5,%6,%7}, {%8,%9}, {%0,%1,%2,%3};"
        : "+f"(d[0]), "+f"(d[1]), "+f"(d[2]), "+f"(d[3])
        : "r"(a[0]), "r"(a[1]), "r"(a[2]), "r"(a[3]), "r"(b[0]), "r"(b[1]));
}
__device__ __forceinline__ void cp16(uint32_t dst, const void* src) {
    asm volatile("cp.async.ca.shared.global [%0], [%1], 16;" :: "r"(dst), "l"(src));
}
#define CP_COMMIT() asm volatile("cp.async.commit_group;" ::: "memory")
#define CP_WAIT(n)  asm volatile("cp.async.wait_group %0;" :: "n"(n) : "memory")
__device__ __forceinline__ uint32_t pack_h2(float a, float b) {
    __half2 t = __floats2half2_rn(a, b);
    return *(uint32_t*)&t;
}

// ---------------- prep: LN1 + y->fp16 + w->fp16 ----------------
__global__ void prep_kernel(const float* __restrict__ x,
                            const float* __restrict__ n1w, const float* __restrict__ n1b,
                            const float* __restrict__ y,
                            const float* __restrict__ qvw, const float* __restrict__ kw,
                            const float* __restrict__ pw,  const float* __restrict__ f1,
                            const float* __restrict__ f2,
                            __half* __restrict__ xn, __half* __restrict__ yh,
                            __half* __restrict__ wdst)
{
    const int b = blockIdx.x, tid = threadIdx.x;
    if (b < 8192) {
        const int row = b * 2 + (tid >> 7);
        const int r = tid & 127;
        float v = x[row * Cdim + r];
        float s = v, s2 = v * v;
        #pragma unroll
        for (int o = 16; o; o >>= 1) {
            s  += __shfl_xor_sync(0xffffffffu, s,  o);
            s2 += __shfl_xor_sync(0xffffffffu, s2, o);
        }
        __shared__ float ss[8], ss2[8];
        const int wrp = tid >> 5;
        if ((tid & 31) == 0) { ss[wrp] = s; ss2[wrp] = s2; }
        __syncthreads();
        const int base = (tid >> 7) * 4;
        s  = ss[base]  + ss[base + 1]  + ss[base + 2]  + ss[base + 3];
        s2 = ss2[base] + ss2[base + 1] + ss2[base + 2] + ss2[base + 3];
        float mu  = s * (1.0f / Cdim);
        float var = s2 * (1.0f / Cdim) - mu * mu;
        float rr = (v - mu) * rsqrtf(var + 1e-5f) * n1w[r] + n1b[r];
        xn[row * Cdim + r] = __float2half(rr);
    } else if (b < 12288) {
        const int i = (b - 8192) * 512 + tid * 2;
        yh[i]     = __float2half(y[i]);
        yh[i + 1] = __float2half(y[i + 1]);
    } else {
        const int wi = (b - 12288) * 512 + tid * 2;
        #pragma unroll
        for (int e = 0; e < 2; e++) {
            int q = wi + e;
            if (q < 196608) {
                float v;
                if      (q < 32768)  v = qvw[q];
                else if (q < 49152)  v = kw [q - 32768];
                else if (q < 65536)  v = pw [q - 49152];
                else if (q < 131072) v = f1 [q - 65536];
                else                 v = f2 [q - 131072];
                wdst[q] = __float2half(v);
            }
        }
    }
}

// ---------------- GEMM core 64x64 (fc2) ----------
#define OFF_W  9216
#define STAGE  18432
#define GSMEM  (2 * STAGE)

template <int KTOT>
__device__ __forceinline__ void gemm_core(
    const __half* __restrict__ A, const __half* __restrict__ W,
    int bm, int bn, uint32_t sb, float acc[2][4][4])
{
    const int tid = threadIdx.x, lane = tid & 31, wid = tid >> 5;
    const int wm = wid & 1, wn = wid >> 1;
    const int nch = KTOT / 64;

    #pragma unroll
    for (int i = 0; i < 2; i++)
        #pragma unroll
        for (int j = 0; j < 4; j++)
            #pragma unroll
            for (int q = 0; q < 4; q++) acc[i][j][q] = 0.0f;

    const uint32_t aRow = wm * 32 + (lane & 15);
    const uint32_t aKof = ((lane >> 4) << 3);
    const uint32_t bRow = wn * 32 + ((lane >> 4) << 3) + (lane & 7);
    const uint32_t bKof = ((lane >> 3) & 1) << 3;

    #pragma unroll
    for (int t = tid; t < 1024; t += 128) {
        const int isW = t >> 9;
        const int u = t & 511, row = u >> 3, c8 = u & 7;
        const uint32_t dst = sb + isW * OFF_W + row * 144 + c8 * 16;
        const __half* src = (isW ? W : A) +
            (size_t)((isW ? bn : bm) * 64 + row) * KTOT + c8 * 8;
        cp16(dst, src);
    }
    CP_COMMIT();

    for (int ch = 0; ch < nch; ch++) {
        if (ch + 1 < nch) {
            const uint32_t st = sb + ((ch + 1) & 1) * STAGE;
            const int kb = (ch + 1) * 64;
            #pragma unroll
            for (int t = tid; t < 1024; t += 128) {
                const int isW = t >> 9;
                const int u = t & 511, row = u >> 3, c8 = u & 7;
                const uint32_t dst = st + isW * OFF_W + row * 144 + c8 * 16;
                const __half* src = (isW ? W : A) +
                    (size_t)((isW ? bn : bm) * 64 + row) * KTOT + kb + c8 * 8;
                cp16(dst, src);
            }
            CP_COMMIT();
            CP_WAIT(1);
        } else {
            CP_WAIT(0);
        }
        __syncthreads();

        const uint32_t st = sb + (ch & 1) * STAGE;
        #pragma unroll
        for (int ks = 0; ks < 4; ks++) {
            const uint32_t aoff = st + (aRow * 72 + ks * 16 + aKof) * 2;
            const uint32_t boff = st + OFF_W + (bRow * 72 + ks * 16 + bKof) * 2;
            uint32_t a0[4], a1[4], w0[4], w1[4];
            ldm_x4(a0[0], a0[1], a0[2], a0[3], aoff);
            ldm_x4(a1[0], a1[1], a1[2], a1[3], aoff + 16 * 144);
            ldm_x4(w0[0], w0[1], w0[2], w0[3], boff);
            ldm_x4(w1[0], w1[1], w1[2], w1[3], boff + 16 * 144);

            mma_f16(acc[0][0], a0, w0); mma_f16(acc[0][1], a0, w0 + 2);
            mma_f16(acc[0][2], a0, w1); mma_f16(acc[0][3], a0, w1 + 2);
            mma_f16(acc[1][0], a1, w0); mma_f16(acc[1][1], a1, w0 + 2);
            mma_f16(acc[1][2], a1, w1); mma_f16(acc[1][3], a1, w1 + 2);
        }
        __syncthreads();
    }
}

// ---------------- GEMM core 64x128 (qvk, proj) ----------
#define OFF_W2 9216
#define STAGE2 27648
#define GSMEM2 (2 * STAGE2)

template <int KTOT>
__device__ __forceinline__ void gemm_core_n128(
    const __half* __restrict__ A, const __half* __restrict__ W,
    int bm, uint32_t sb, float acc[2][8][4])
{
    const int tid = threadIdx.x, lane = tid & 31, wid = tid >> 5;
    const int wm = wid & 1, wn = wid >> 1;
    const int nch = KTOT / 64;

    #pragma unroll
    for (int i = 0; i < 2; i++)
        #pragma unroll
        for (int j = 0; j < 8; j++)
            #pragma unroll
            for (int q = 0; q < 4; q++) acc[i][j][q] = 0.0f;

    const uint32_t aRow = wm * 32 + (lane & 15);
    const uint32_t aKof = ((lane >> 4) << 3);
    const uint32_t bRow = wn * 64 + ((lane >> 4) << 3) + (lane & 7);
    const uint32_t bKof = ((lane >> 3) & 1) << 3;

    #pragma unroll
    for (int t = tid; t < 1536; t += 128) {
        const int isW = t >= 512;
        const int u = isW ? (t - 512) : t;
        const int row = u >> 3, c8 = u & 7;
        const uint32_t dst = sb + (isW ? OFF_W2 : 0) + row * 144 + c8 * 16;
        const __half* src = isW ? (W + (size_t)row * KTOT + c8 * 8)
                                : (A + (size_t)(bm * 64 + row) * KTOT + c8 * 8);
        cp16(dst, src);
    }
    CP_COMMIT();

    for (int ch = 0; ch < nch; ch++) {
        if (ch + 1 < nch) {
            const uint32_t st = sb + ((ch + 1) & 1) * STAGE2;
            const int kb = (ch + 1) * 64;
            #pragma unroll
            for (int t = tid; t < 1536; t += 128) {
                const int isW = t >= 512;
                const int u = isW ? (t - 512) : t;
                const int row = u >> 3, c8 = u & 7;
                const uint32_t dst = st + (isW ? OFF_W2 : 0) + row * 144 + c8 * 16;
                const __half* src = isW ? (W + (size_t)row * KTOT + kb + c8 * 8)
                                        : (A + (size_t)(bm * 64 + row) * KTOT + kb + c8 * 8);
                cp16(dst, src);
            }
            CP_COMMIT();
            CP_WAIT(1);
        } else {
            CP_WAIT(0);
        }
        __syncthreads();

        const uint32_t st = sb + (ch & 1) * STAGE2;
        #pragma unroll
        for (int ks = 0; ks < 4; ks++) {
            const uint32_t aoff = st + (aRow * 72 + ks * 16 + aKof) * 2;
            uint32_t a0[4], a1[4];
            ldm_x4(a0[0], a0[1], a0[2], a0[3], aoff);
            ldm_x4(a1[0], a1[1], a1[2], a1[3], aoff + 16 * 144);
            uint32_t wf[4][4];
            #pragma unroll
            for (int nf4 = 0; nf4 < 4; nf4++) {
                const uint32_t boff = st + OFF_W2 +
                    ((bRow + nf4 * 16) * 72 + ks * 16 + bKof) * 2;
                ldm_x4(wf[nf4][0], wf[nf4][1], wf[nf4][2], wf[nf4][3], boff);
            }
            #pragma unroll
            for (int nf4 = 0; nf4 < 4; nf4++) {
                mma_f16(acc[0][nf4 * 2],     a0, wf[nf4]);
                mma_f16(acc[0][nf4 * 2 + 1], a0, wf[nf4] + 2);
            }
            #pragma unroll
            for (int nf4 = 0; nf4 < 4; nf4++) {
                mma_f16(acc[1][nf4 * 2],     a1, wf[nf4]);
                mma_f16(acc[1][nf4 * 2 + 1], a1, wf[nf4] + 2);
            }
        }
        __syncthreads();
    }
}

// ---------------- fused qv + k GEMM (n128 tiles) ---------------------------
__global__ __launch_bounds__(128, 4)
void gemm_qvk(const __half* __restrict__ xn, const __half* __restrict__ yh,
              const __half* __restrict__ wbuf,
              const float* __restrict__ qv_b, const float* __restrict__ k_b,
              __half* __restrict__ qout,
              __half* __restrict__ vout, __half* __restrict__ kout)
{
    extern __shared__ __align__(16) char dsm[];
    const uint32_t sb = smem_u32(dsm);
    const int bx = blockIdx.x, bm = blockIdx.y;
    float acc[2][8][4];
    const __half* A = (bx == 2) ? yh : xn;
    const __half* W = (bx == 0) ? wbuf : (bx == 1 ? wbuf + 16384 : wbuf + 32768);
    gemm_core_n128<128>(A, W, bm, sb, acc);

    const float* bias = (bx == 0) ? qv_b : (bx == 1 ? qv_b + 128 : k_b);
    __half* outp = (bx == 0) ? qout : (bx == 1 ? vout : kout);
    const float qs = (bx == 0) ? QSCALE : 1.0f;

    const int tid = threadIdx.x, lane = tid & 31, wid = tid >> 5;
    const int wm = wid & 1, wn = wid >> 1;
    #pragma unroll
    for (int mf = 0; mf < 2; mf++) {
        const int row0 = bm * 64 + wm * 32 + mf * 16 + (lane >> 2);
        #pragma unroll
        for (int nf = 0; nf < 8; nf++) {
            const int col = wn * 64 + nf * 8 + (lane & 3) * 2;
            float* a = acc[mf][nf];
            float2 bi = *(const float2*)&bias[col];
            *(uint32_t*)&outp[(size_t)row0 * 128 + col] =
                pack_h2((a[0] + bi.x) * qs, (a[1] + bi.y) * qs);
            *(uint32_t*)&outp[(size_t)(row0 + 8) * 128 + col] =
                pack_h2((a[2] + bi.x) * qs, (a[3] + bi.y) * qs);
        }
    }
}

// ------- proj GEMM + residual + register-LN2 + fused fc1(GELU) -------------
// xn kept in smem (A-stage layout); fc1 W streamed through stage buffers.
#define XNOFF 55296
#define GSMEM4 (XNOFF + 18432)   // 73728 -> 3 CTAs/SM

__global__ __launch_bounds__(128, 3)
void gemm_proj_fc1(const __half* __restrict__ A, const __half* __restrict__ W,
                   const float* __restrict__ bias, const float* __restrict__ res,
                   const float* __restrict__ n2w, const float* __restrict__ n2b,
                   const __half* __restrict__ w1, const float* __restrict__ b1,
                   float* __restrict__ x2out, __half* __restrict__ hout)
{
    extern __shared__ __align__(16) char dsm[];
    const uint32_t sb = smem_u32(dsm);
    const int bm = blockIdx.x;
    float acc[2][8][4];
    gemm_core_n128<128>(A, W, bm, sb, acc);

    const int tid = threadIdx.x, lane = tid & 31, wid = tid >> 5;
    const int wm = wid & 1, wn = wid >> 1;
    float2* part = (float2*)dsm;     // [2 halves][64 rows] (s, s2); stages dead

    // pass 1: v = acc + bias + res; write x2; fold into acc; row partials
    float rs_[2][2], rs2_[2][2];
    #pragma unroll
    for (int mf = 0; mf < 2; mf++) {
        const int lr = wm * 32 + mf * 16 + (lane >> 2);
        const int grow = bm * 64 + lr;
        float s0 = 0.f, s20 = 0.f, s1 = 0.f, s21 = 0.f;
        #pragma unroll
        for (int nf = 0; nf < 8; nf++) {
            const int col = wn * 64 + nf * 8 + (lane & 3) * 2;
            float* a = acc[mf][nf];
            float2 bi = *(const float2*)&bias[col];
            float2 r0 = *(const float2*)&res[(size_t)grow * 128 + col];
            float2 r1 = *(const float2*)&res[(size_t)(grow + 8) * 128 + col];
            float v0 = a[0] + bi.x + r0.x, v1 = a[1] + bi.y + r0.y;
            float v2 = a[2] + bi.x + r1.x, v3 = a[3] + bi.y + r1.y;
            *(float2*)&x2out[(size_t)grow * 128 + col]       = make_float2(v0, v1);
            *(float2*)&x2out[(size_t)(grow + 8) * 128 + col] = make_float2(v2, v3);
            a[0] = v0; a[1] = v1; a[2] = v2; a[3] = v3;
            s0 += v0 + v1; s20 += v0 * v0 + v1 * v1;
            s1 += v2 + v3; s21 += v2 * v2 + v3 * v3;
        }
        #pragma unroll
        for (int o = 1; o <= 2; o <<= 1) {
            s0  += __shfl_xor_sync(0xffffffffu, s0,  o);
            s20 += __shfl_xor_sync(0xffffffffu, s20, o);
            s1  += __shfl_xor_sync(0xffffffffu, s1,  o);
            s21 += __shfl_xor_sync(0xffffffffu, s21, o);
        }
        rs_[mf][0] = s0; rs2_[mf][0] = s20;
        rs_[mf][1] = s1; rs2_[mf][1] = s21;
        if ((lane & 3) == 0) {
            part[wn * 64 + lr]     = make_float2(s0, s20);
            part[wn * 64 + lr + 8] = make_float2(s1, s21);
        }
    }
    __syncthreads();

    // pass 2: normalize from registers, write xn to SMEM in A-stage layout
    #pragma unroll
    for (int mf = 0; mf < 2; mf++) {
        const int lr = wm * 32 + mf * 16 + (lane >> 2);
        #pragma unroll
        for (int hh = 0; hh < 2; hh++) {
            float2 oth = part[(1 - wn) * 64 + lr + hh * 8];
            const float s  = rs_[mf][hh]  + oth.x;
            const float s2 = rs2_[mf][hh] + oth.y;
            const float mu  = s * (1.0f / 128.0f);
            const float var = s2 * (1.0f / 128.0f) - mu * mu;
            const float rsq = rsqrtf(var + 1e-5f);
            const int lrow = lr + hh * 8;           // local row 0..63
            #pragma unroll
            for (int nf = 0; nf < 8; nf++) {
                const int col = wn * 64 + nf * 8 + (lane & 3) * 2;
                float2 wv = *(const float2*)&n2w[col];
                float2 bv = *(const float2*)&n2b[col];
                float* a = acc[mf][nf];
                const float va = a[hh * 2], vb = a[hh * 2 + 1];
                const int inc = nf * 8 + (lane & 3) * 2;   // col within 64-chunk
                *(uint32_t*)(dsm + XNOFF + wn * 9216 + lrow * 144 + inc * 2) =
                    pack_h2((va - mu) * rsq * wv.x + bv.x,
                            (vb - mu) * rsq * wv.y + bv.y);
            }
        }
    }
    __syncthreads();

    // ---- fc1 phase: A = xn tile in smem, W streamed (8 stages) ----
    const uint32_t aRow = wm * 32 + (lane & 15);
    const uint32_t aKof = ((lane >> 4) << 3);
    const uint32_t bRow = wn * 64 + ((lane >> 4) << 3) + (lane & 7);
    const uint32_t bKof = ((lane >> 3) & 1) << 3;

    // stage 0 (bn=0, ch=0)
    #pragma unroll
    for (int t = tid; t < 1024; t += 128) {
        const int row = t >> 3, c8 = t & 7;
        cp16(sb + row * 144 + c8 * 16, w1 + (size_t)row * 128 + c8 * 8);
    }
    CP_COMMIT();

    float fa[2][8][4];
    #pragma unroll
    for (int i = 0; i < 2; i++)
        #pragma unroll
        for (int j = 0; j < 8; j++)
            #pragma unroll
            for (int q = 0; q < 4; q++) fa[i][j][q] = 0.0f;

    for (int s = 0; s < 8; s++) {
        const int bn = s >> 1, ch = s & 1;
        if (s + 1 < 8) {
            const int bn2 = (s + 1) >> 1, ch2 = (s + 1) & 1;
            const uint32_t st2 = sb + ((s + 1) & 1) * 18432;
            #pragma unroll
            for (int t = tid; t < 1024; t += 128) {
                const int row = t >> 3, c8 = t & 7;
                cp16(st2 + row * 144 + c8 * 16,
                     w1 + (size_t)(bn2 * 128 + row) * 128 + ch2 * 64 + c8 * 8);
            }
            CP_COMMIT();
            CP_WAIT(1);
        } else {
            CP_WAIT(0);
        }
        __syncthreads();

        const uint32_t st = sb + (s & 1) * 18432;
        #pragma unroll
        for (int ks = 0; ks < 4; ks++) {
            const uint32_t aoff = sb + XNOFF + (ch ? 9216 : 0)
                                + (aRow * 72 + ks * 16 + aKof) * 2;
            uint32_t a0[4], a1[4];
            ldm_x4(a0[0], a0[1], a0[2], a0[3], aoff);
            ldm_x4(a1[0], a1[1], a1[2], a1[3], aoff + 16 * 144);
            uint32_t wf[4][4];
            #pragma unroll
            for (int nf4 = 0; nf4 < 4; nf4++) {
                const uint32_t boff = st + ((bRow + nf4 * 16) * 72 + ks * 16 + bKof) * 2;
                ldm_x4(wf[nf4][0], wf[nf4][1], wf[nf4][2], wf[nf4][3], boff);
            }
            #pragma unroll
            for (int nf4 = 0; nf4 < 4; nf4++) {
                mma_f16(fa[0][nf4 * 2],     a0, wf[nf4]);
                mma_f16(fa[0][nf4 * 2 + 1], a0, wf[nf4] + 2);
            }
            #pragma unroll
            for (int nf4 = 0; nf4 < 4; nf4++) {
                mma_f16(fa[1][nf4 * 2],     a1, wf[nf4]);
                mma_f16(fa[1][nf4 * 2 + 1], a1, wf[nf4] + 2);
            }
        }
        __syncthreads();

        if (ch == 1) {   // finished bn: GELU epilogue, reset accumulators
            #pragma unroll
            for (int mf = 0; mf < 2; mf++) {
                const int row0 = bm * 64 + wm * 32 + mf * 16 + (lane >> 2);
                #pragma unroll
                for (int nf = 0; nf < 8; nf++) {
                    const int col = bn * 128 + wn * 64 + nf * 8 + (lane & 3) * 2;
                    float* a = fa[mf][nf];
                    float2 bi = *(const float2*)&b1[col];
                    float v[4];
                    v[0] = a[0] + bi.x; v[1] = a[1] + bi.y;
                    v[2] = a[2] + bi.x; v[3] = a[3] + bi.y;
                    #pragma unroll
                    for (int e = 0; e < 4; e++)
                        v[e] = 0.5f * v[e] * (1.0f + erff(v[e] * 0.70710678118654752f));
                    *(uint32_t*)&hout[(size_t)row0 * 512 + col]       = pack_h2(v[0], v[1]);
                    *(uint32_t*)&hout[(size_t)(row0 + 8) * 512 + col] = pack_h2(v[2], v[3]);
                    a[0] = 0.f; a[1] = 0.f; a[2] = 0.f; a[3] = 0.f;
                }
            }
        }
    }
}

// ---------------- fc2 (64x64, K=512): GEMM + residual -> out ---------------
__global__ __launch_bounds__(128, 5)
void gemm_res2(const __half* __restrict__ A, const __half* __restrict__ W,
               const float* __restrict__ bias, const float* __restrict__ res,
               float* __restrict__ outf)
{
    extern __shared__ __align__(16) char dsm[];
    const uint32_t sb = smem_u32(dsm);
    const int bn = blockIdx.x, bm = blockIdx.y;
    float acc[2][4][4];
    gemm_core<512>(A, W, bm, bn, sb, acc);

    const int tid = threadIdx.x, lane = tid & 31, wid = tid >> 5;
    const int wm = wid & 1, wn = wid >> 1;
    #pragma unroll
    for (int mf = 0; mf < 2; mf++) {
        const int row0 = bm * 64 + wm * 32 + mf * 16 + (lane >> 2);
        #pragma unroll
        for (int nf = 0; nf < 4; nf++) {
            const int col = bn * 64 + wn * 32 + nf * 8 + (lane & 3) * 2;
            float* a = acc[mf][nf];
            float2 bi = *(const float2*)&bias[col];
            float2 r0 = *(const float2*)&res[(size_t)row0 * 128 + col];
            float2 r1 = *(const float2*)&res[(size_t)(row0 + 8) * 128 + col];
            *(float2*)&outf[(size_t)row0 * 128 + col] =
                make_float2(a[0] + bi.x + r0.x, a[1] + bi.y + r0.y);
            *(float2*)&outf[(size_t)(row0 + 8) * 128 + col] =
                make_float2(a[2] + bi.x + r1.x, a[3] + bi.y + r1.y);
        }
    }
}

// ------- neighborhood attention: full half2 arithmetic (proven) --------
#define NBW 22
#define NBH 14
#define NBR (NBW * NBH)
#define KVP 40

__global__ __launch_bounds__(128)
void attn_kernel(const __half* __restrict__ qbuf,
                 const __half* __restrict__ vbuf,
                 const __half* __restrict__ kbuf,
                 const float* __restrict__ rpb,
                 __half* __restrict__ obuf)
{
    __shared__ __align__(16) __half kv_s[NBR * KVP];
    __shared__ float rpb_s[RPBW * RPBW];

    const int hd = blockIdx.z;
    const int bw = blockIdx.x * 16, bh = blockIdx.y * 8;
    const int tid = threadIdx.x;
    const int px = tid & 15, py = tid >> 4;
    const int h = bh + py, w = bw + px;
    const int o_h = min(max(bh - 3, 0), Hdim - NBH);
    const int o_w = min(max(bw - 3, 0), Wdim - NBW);

    for (int i = tid; i < RPBW * RPBW; i += 128) rpb_s[i] = rpb[hd * RPBW * RPBW + i];

    for (int idx = tid; idx < NBR * 4; idx += 128) {
        const int rr = idx >> 2, j = idx & 3;
        const int gh = o_h + rr / NBW, gw = o_w + rr % NBW;
        *(uint4*)&kv_s[rr * KVP + j * 8] =
            *(const uint4*)&kbuf[(size_t)(gh * Wdim + gw) * Cdim + hd * HD + j * 8];
    }
    __syncthreads();

    uint32_t qw[16];
    {
        const uint4* qp = (const uint4*)&qbuf[(size_t)(h * Wdim + w) * Cdim + hd * HD];
        #pragma unroll
        for (int j = 0; j < 4; j++) {
            uint4 t = qp[j];
            qw[j * 4] = t.x; qw[j * 4 + 1] = t.y; qw[j * 4 + 2] = t.z; qw[j * 4 + 3] = t.w;
        }
    }

    const int sh = min(max(h - 3, 0), Hdim - KW);
    const int sw = min(max(w - 3, 0), Wdim - KW);
    const int lr0 = sh - o_h, lc0 = sw - o_w;
    const int rh0 = sh - h + 6, rw0 = sw - w + 6;

    float p[KK];
    #pragma unroll
    for (int a = 0; a < KW; a++) {
        #pragma unroll
        for (int c = 0; c < KW; c++) {
            const uint4* kp = (const uint4*)&kv_s[((lr0 + a) * NBW + lc0 + c) * KVP];
            __half2 d0 = __float2half2_rn(0.f), d1 = d0, d2 = d0, d3 = d0;
            #pragma unroll
            for (int j = 0; j < 4; j++) {
                uint4 t = kp[j];
                d0 = __hfma2(*(__half2*)&qw[j*4+0], *(__half2*)&t.x, d0);
                d1 = __hfma2(*(__half2*)&qw[j*4+1], *(__half2*)&t.y, d1);
                d2 = __hfma2(*(__half2*)&qw[j*4+2], *(__half2*)&t.z, d2);
                d3 = __hfma2(*(__half2*)&qw[j*4+3], *(__half2*)&t.w, d3);
            }
            __half2 ds = __hadd2(__hadd2(d0, d1), __hadd2(d2, d3));
            p[a * KW + c] = __low2float(ds) + __high2float(ds)
                          + rpb_s[(rh0 + a) * RPBW + rw0 + c];
        }
    }

    float mx = -1e30f;
    #pragma unroll
    for (int n = 0; n < KK; n++) mx = fmaxf(mx, p[n]);
    float ssum = 0.0f;
    #pragma unroll
    for (int n = 0; n < KK; n++) { p[n] = __expf(p[n] - mx); ssum += p[n]; }
    const float inv = __fdividef(1.0f, ssum);
    __syncthreads();

    for (int idx = tid; idx < NBR * 4; idx += 128) {
        const int rr = idx >> 2, j = idx & 3;
        const int gh = o_h + rr / NBW, gw = o_w + rr % NBW;
        *(uint4*)&kv_s[rr * KVP + j * 8] =
            *(const uint4*)&vbuf[(size_t)(gh * Wdim + gw) * Cdim + hd * HD + j * 8];
    }
    __syncthreads();

    __half2 acc2[16];
    #pragma unroll
    for (int j = 0; j < 16; j++) acc2[j] = __float2half2_rn(0.f);
    #pragma unroll
    for (int a = 0; a < KW; a++) {
        #pragma unroll
        for (int c = 0; c < KW; c++) {
            const __half2 ph = __float2half2_rn(p[a * KW + c] * inv);
            const uint4* vp = (const uint4*)&kv_s[((lr0 + a) * NBW + lc0 + c) * KVP];
            #pragma unroll
            for (int j = 0; j < 4; j++) {
                uint4 t = vp[j];
                acc2[j*4+0] = __hfma2(ph, *(__half2*)&t.x, acc2[j*4+0]);
                acc2[j*4+1] = __hfma2(ph, *(__half2*)&t.y, acc2[j*4+1]);
                acc2[j*4+2] = __hfma2(ph, *(__half2*)&t.z, acc2[j*4+2]);
                acc2[j*4+3] = __hfma2(ph, *(__half2*)&t.w, acc2[j*4+3]);
            }
        }
    }
    const size_t base = (size_t)(h * Wdim + w) * Cdim + hd * HD;
    #pragma unroll
    for (int j = 0; j < 16; j++)
        *(uint32_t*)&obuf[base + j * 2] = *(uint32_t*)&acc2[j];
}

// ---------------- launch -----------------
extern "C" void kernel_launch(void* const* d_in, const int* in_sizes, int n_in,
                              void* d_out, int out_size)
{
    const float* x      = (const float*)d_in[0];
    const float* y      = (const float*)d_in[1];
    const float* qv_w   = (const float*)d_in[2];
    const float* qv_b   = (const float*)d_in[3];
    const float* k_w    = (const float*)d_in[4];
    const float* k_b    = (const float*)d_in[5];
    const float* rpb    = (const float*)d_in[6];
    const float* proj_w = (const float*)d_in[7];
    const float* proj_b = (const float*)d_in[8];
    const float* n1_w   = (const float*)d_in[9];
    const float* n1_b   = (const float*)d_in[10];
    const float* n2_w   = (const float*)d_in[11];
    const float* n2_b   = (const float*)d_in[12];
    const float* fc1_w  = (const float*)d_in[13];
    const float* fc1_b  = (const float*)d_in[14];
    const float* fc2_w  = (const float*)d_in[15];
    const float* fc2_b  = (const float*)d_in[16];
    float* out = (float*)d_out;

    float* p_x2;
    __half *p_qh, *p_vh, *p_kh, *xn, *yhh, *att, *hb, *wb;
    cudaGetSymbolAddress((void**)&p_x2, g_x2);
    cudaGetSymbolAddress((void**)&p_qh, g_qh);
    cudaGetSymbolAddress((void**)&p_vh, g_vh);
    cudaGetSymbolAddress((void**)&p_kh, g_kh);
    cudaGetSymbolAddress((void**)&xn,  s_xn);
    cudaGetSymbolAddress((void**)&yhh, s_yh);
    cudaGetSymbolAddress((void**)&att, s_att);
    cudaGetSymbolAddress((void**)&hb,  s_h);
    cudaGetSymbolAddress((void**)&wb,  s_w);

    cudaFuncSetAttribute(gemm_qvk,      cudaFuncAttributeMaxDynamicSharedMemorySize, GSMEM2);
    cudaFuncSetAttribute(gemm_proj_fc1, cudaFuncAttributeMaxDynamicSharedMemorySize, GSMEM4);
    cudaFuncSetAttribute(gemm_res2,     cudaFuncAttributeMaxDynamicSharedMemorySize, GSMEM);

    // 1) prep: LN1(x) + y->fp16 + w->fp16
    prep_kernel<<<12672, 256>>>(x, n1_w, n1_b, y, qv_w, k_w, proj_w, fc1_w, fc2_w,
                                xn, yhh, wb);

    // 2) fused qv + k GEMMs (n128 tiles; bx=0 q, bx=1 v, bx=2 k)
    gemm_qvk<<<dim3(3, NPIX / 64), 128, GSMEM2>>>(
        xn, yhh, wb, qv_b, k_b, p_qh, p_vh, p_kh);

    // 3) neighborhood attention (half2)
    attn_kernel<<<dim3(Wdim / 16, Hdim / 8, HEADS), 128>>>(p_qh, p_vh, p_kh, rpb, att);

    // 4) proj GEMM + residual + LN2 + fc1 + GELU (fully fused)
    gemm_proj_fc1<<<NPIX / 64, 128, GSMEM4>>>(
        att, wb + 49152, proj_b, x, n2_w, n2_b,
        wb + 65536, fc1_b, p_x2, hb);

    // 5) fc2 + residual -> out
    gemm_res2<<<dim3(2, NPIX / 64), 128, GSMEM>>>(
        hb, wb + 131072, fc2_b, p_x2, out);
}